// round 1
// baseline (speedup 1.0000x reference)
#include <cuda_runtime.h>

// Problem constants
constexpr int Bn = 4;
constexpr int Sn = 2048;
constexpr int En = 512;
constexpr int Hn = 8;
constexpr int Dn = 64;
constexpr int Mtot = Bn * Sn;   // 8192
constexpr int BH = Bn * Hn;     // 32

constexpr float SCALE = 0.125f;                 // 1/sqrt(64)
constexpr float LOG2_DECAY = -0.07400058144377693f; // log2(0.95)
constexpr float LOG2E = 1.4426950408889634f;

// Scratch (device globals — no allocation allowed)
__device__ float g_q[BH * Sn * Dn];
__device__ float g_k[BH * Sn * Dn];
__device__ float g_v[BH * Sn * Dn];
__device__ float g_attn[BH * Sn * Dn];

// ---------------------------------------------------------------------------
// Kernel 1: fused QKV projection.
// out[m,n] = sum_k x[m,k] * W[n,k] + b[n], scattered into [B,H,S,D].
// Tiles: BM=64, BN=64, BK=32. 256 threads, 4x4 outputs per thread.
// ---------------------------------------------------------------------------
__global__ void __launch_bounds__(256, 2)
qkv_proj_kernel(const float* __restrict__ x,
                const float* __restrict__ Wq, const float* __restrict__ bq,
                const float* __restrict__ Wk, const float* __restrict__ bk,
                const float* __restrict__ Wv, const float* __restrict__ bv)
{
    const float* W;
    const float* bias;
    float* dst;
    if (blockIdx.z == 0)      { W = Wq; bias = bq; dst = g_q; }
    else if (blockIdx.z == 1) { W = Wk; bias = bk; dst = g_k; }
    else                      { W = Wv; bias = bv; dst = g_v; }

    __shared__ float sA[32][68];  // [k][m], padded
    __shared__ float sB[32][68];  // [k][n], padded

    const int tid = threadIdx.x;
    const int tx = tid & 15;
    const int ty = tid >> 4;
    const int m0 = blockIdx.y * 64;
    const int n0 = blockIdx.x * 64;

    float acc[4][4] = {};

    const int lr = tid >> 3;          // 0..31
    const int lc = (tid & 7) * 4;     // 0..28

    for (int k0 = 0; k0 < En; k0 += 32) {
        // Load A tile (64 x 32) transposed into sA[k][m]
        {
            float4 a0 = *(const float4*)&x[(m0 + lr) * En + k0 + lc];
            float4 a1 = *(const float4*)&x[(m0 + lr + 32) * En + k0 + lc];
            sA[lc + 0][lr] = a0.x; sA[lc + 1][lr] = a0.y;
            sA[lc + 2][lr] = a0.z; sA[lc + 3][lr] = a0.w;
            sA[lc + 0][lr + 32] = a1.x; sA[lc + 1][lr + 32] = a1.y;
            sA[lc + 2][lr + 32] = a1.z; sA[lc + 3][lr + 32] = a1.w;

            float4 b0 = *(const float4*)&W[(n0 + lr) * En + k0 + lc];
            float4 b1 = *(const float4*)&W[(n0 + lr + 32) * En + k0 + lc];
            sB[lc + 0][lr] = b0.x; sB[lc + 1][lr] = b0.y;
            sB[lc + 2][lr] = b0.z; sB[lc + 3][lr] = b0.w;
            sB[lc + 0][lr + 32] = b1.x; sB[lc + 1][lr + 32] = b1.y;
            sB[lc + 2][lr + 32] = b1.z; sB[lc + 3][lr + 32] = b1.w;
        }
        __syncthreads();

        #pragma unroll
        for (int kk = 0; kk < 32; ++kk) {
            float4 av = *(const float4*)&sA[kk][ty * 4];
            float4 bv = *(const float4*)&sB[kk][tx * 4];
            float a[4] = {av.x, av.y, av.z, av.w};
            float b[4] = {bv.x, bv.y, bv.z, bv.w};
            #pragma unroll
            for (int i = 0; i < 4; ++i)
                #pragma unroll
                for (int j = 0; j < 4; ++j)
                    acc[i][j] += a[i] * b[j];
        }
        __syncthreads();
    }

    // Epilogue: add bias, scatter into [B,H,S,D]
    #pragma unroll
    for (int i = 0; i < 4; ++i) {
        int m = m0 + ty * 4 + i;
        int bb = m >> 11;           // m / 2048
        int ss = m & 2047;
        #pragma unroll
        for (int j = 0; j < 4; ++j) {
            int n = n0 + tx * 4 + j;
            int hh = n >> 6;
            int dd = n & 63;
            dst[(((bb * Hn + hh) * Sn) + ss) * Dn + dd] = acc[i][j] + bias[n];
        }
    }
}

// ---------------------------------------------------------------------------
// Kernel 2: flash-style attention with multiplicative decay mask.
// One CTA = one (bh, 64-query tile). 256 threads (16x16), 4x4 per thread.
// Shared: sQ[64d][64i], sKP[64][68] (K transposed, reused for P row-major),
//         sV[64j][64d].
// ---------------------------------------------------------------------------
constexpr int SMEM_ATTN = (64 * 64 + 64 * 68 + 64 * 64) * 4; // 50176 B

__global__ void __launch_bounds__(256, 1)
attn_kernel()
{
    extern __shared__ float sm[];
    float (*sQ)[64]  = (float(*)[64])(sm);                     // [d][i]
    float (*sKP)[68] = (float(*)[68])(sm + 64 * 64);           // K:[d][j] / P:[i][j]
    float (*sV)[64]  = (float(*)[64])(sm + 64 * 64 + 64 * 68); // [j][d]

    const int bh = blockIdx.y;
    const int q0 = blockIdx.x * 64;
    const float* Q = g_q + bh * Sn * Dn;
    const float* K = g_k + bh * Sn * Dn;
    const float* V = g_v + bh * Sn * Dn;
    float* O = g_attn + bh * Sn * Dn;

    const int tid = threadIdx.x;
    const int tx = tid & 15;
    const int ty = tid >> 4;

    const int lr = tid >> 2;          // 0..63
    const int lc = (tid & 3) * 16;    // 0,16,32,48

    // Load Q tile (64 rows x 64 d), transposed into sQ[d][i]
    #pragma unroll
    for (int u = 0; u < 4; ++u) {
        float4 qv = *(const float4*)&Q[(q0 + lr) * Dn + lc + u * 4];
        sQ[lc + u * 4 + 0][lr] = qv.x;
        sQ[lc + u * 4 + 1][lr] = qv.y;
        sQ[lc + u * 4 + 2][lr] = qv.z;
        sQ[lc + u * 4 + 3][lr] = qv.w;
    }

    float m_i[4], l_i[4], o[4][4];
    #pragma unroll
    for (int i = 0; i < 4; ++i) {
        m_i[i] = -1e30f;
        l_i[i] = 0.f;
        #pragma unroll
        for (int j = 0; j < 4; ++j) o[i][j] = 0.f;
    }

    for (int kt = 0; kt < Sn / 64; ++kt) {
        const int k0 = kt * 64;
        __syncthreads();  // previous tile's P/V consumers done (also orders Q stores, iter 0)

        // Load K (transposed) and V tiles
        #pragma unroll
        for (int u = 0; u < 4; ++u) {
            float4 kv = *(const float4*)&K[(k0 + lr) * Dn + lc + u * 4];
            sKP[lc + u * 4 + 0][lr] = kv.x;
            sKP[lc + u * 4 + 1][lr] = kv.y;
            sKP[lc + u * 4 + 2][lr] = kv.z;
            sKP[lc + u * 4 + 3][lr] = kv.w;
            float4 vv = *(const float4*)&V[(k0 + lr) * Dn + lc + u * 4];
            *(float4*)&sV[lr][lc + u * 4] = vv;
        }
        __syncthreads();

        // Scores: s[i][j] = sum_d Q[i][d] K[j][d]
        float s[4][4] = {};
        #pragma unroll 16
        for (int d = 0; d < 64; ++d) {
            float4 qv = *(const float4*)&sQ[d][ty * 4];
            float4 kv = *(const float4*)&sKP[d][tx * 4];
            float a[4] = {qv.x, qv.y, qv.z, qv.w};
            float b[4] = {kv.x, kv.y, kv.z, kv.w};
            #pragma unroll
            for (int i = 0; i < 4; ++i)
                #pragma unroll
                for (int j = 0; j < 4; ++j)
                    s[i][j] += a[i] * b[j];
        }

        // Scale + decay mask
        #pragma unroll
        for (int i = 0; i < 4; ++i) {
            int gi = q0 + ty * 4 + i;
            #pragma unroll
            for (int j = 0; j < 4; ++j) {
                int gj = k0 + tx * 4 + j;
                int dif = gi - gj;
                if (dif < 0) dif = -dif;
                s[i][j] = s[i][j] * SCALE * exp2f(LOG2_DECAY * (float)dif);
            }
        }

        // Online softmax (row groups = 16 lanes with the same ty)
        float mt[4], rs[4];
        #pragma unroll
        for (int i = 0; i < 4; ++i) {
            float mv = fmaxf(fmaxf(s[i][0], s[i][1]), fmaxf(s[i][2], s[i][3]));
            #pragma unroll
            for (int off = 8; off > 0; off >>= 1)
                mv = fmaxf(mv, __shfl_xor_sync(0xffffffffu, mv, off, 16));
            mt[i] = mv;
        }
        #pragma unroll
        for (int i = 0; i < 4; ++i) {
            float mn = fmaxf(m_i[i], mt[i]);
            float corr = exp2f((m_i[i] - mn) * LOG2E);
            m_i[i] = mn;
            l_i[i] *= corr;
            #pragma unroll
            for (int j = 0; j < 4; ++j) o[i][j] *= corr;
            float r = 0.f;
            #pragma unroll
            for (int j = 0; j < 4; ++j) {
                float p = exp2f((s[i][j] - mn) * LOG2E);
                s[i][j] = p;
                r += p;
            }
            rs[i] = r;
        }
        #pragma unroll
        for (int i = 0; i < 4; ++i) {
            #pragma unroll
            for (int off = 8; off > 0; off >>= 1)
                rs[i] += __shfl_xor_sync(0xffffffffu, rs[i], off, 16);
            l_i[i] += rs[i];
        }

        __syncthreads();  // all reads of sKP-as-K finished

        // Write P row-major into sKP[i][j]
        #pragma unroll
        for (int i = 0; i < 4; ++i)
            *(float4*)&sKP[ty * 4 + i][tx * 4] =
                make_float4(s[i][0], s[i][1], s[i][2], s[i][3]);
        __syncthreads();

        // O += P @ V
        #pragma unroll 8
        for (int j = 0; j < 64; ++j) {
            float4 vv = *(const float4*)&sV[j][tx * 4];
            float p0 = sKP[ty * 4 + 0][j];
            float p1 = sKP[ty * 4 + 1][j];
            float p2 = sKP[ty * 4 + 2][j];
            float p3 = sKP[ty * 4 + 3][j];
            o[0][0] += p0 * vv.x; o[0][1] += p0 * vv.y; o[0][2] += p0 * vv.z; o[0][3] += p0 * vv.w;
            o[1][0] += p1 * vv.x; o[1][1] += p1 * vv.y; o[1][2] += p1 * vv.z; o[1][3] += p1 * vv.w;
            o[2][0] += p2 * vv.x; o[2][1] += p2 * vv.y; o[2][2] += p2 * vv.z; o[2][3] += p2 * vv.w;
            o[3][0] += p3 * vv.x; o[3][1] += p3 * vv.y; o[3][2] += p3 * vv.z; o[3][3] += p3 * vv.w;
        }
    }

    // Epilogue: normalize and store
    #pragma unroll
    for (int i = 0; i < 4; ++i) {
        float inv = 1.0f / l_i[i];
        int row = q0 + ty * 4 + i;
        float4 res = make_float4(o[i][0] * inv, o[i][1] * inv,
                                 o[i][2] * inv, o[i][3] * inv);
        *(float4*)&O[row * Dn + tx * 4] = res;
    }
}

// ---------------------------------------------------------------------------
// Kernel 3: output projection.
// out[m,n] = sum_k attn_gathered[m,k] * Wo[n,k] + bo[n]; out is [B,S,E].
// ---------------------------------------------------------------------------
__global__ void __launch_bounds__(256, 2)
out_proj_kernel(const float* __restrict__ Wo, const float* __restrict__ bo,
                float* __restrict__ out)
{
    __shared__ float sA[32][68];
    __shared__ float sB[32][68];

    const int tid = threadIdx.x;
    const int tx = tid & 15;
    const int ty = tid >> 4;
    const int m0 = blockIdx.y * 64;
    const int n0 = blockIdx.x * 64;

    float acc[4][4] = {};

    const int lr = tid >> 3;
    const int lc = (tid & 7) * 4;

    for (int k0 = 0; k0 < En; k0 += 32) {
        {
            // Gather A from g_attn: A[m][k] = attn[b][h][s][d]
            #pragma unroll
            for (int half = 0; half < 2; ++half) {
                int m = m0 + lr + half * 32;
                int bb = m >> 11;
                int ss = m & 2047;
                int k = k0 + lc;
                int hh = k >> 6;
                int dd = k & 63;
                float4 a = *(const float4*)&g_attn[(((bb * Hn + hh) * Sn) + ss) * Dn + dd];
                sA[lc + 0][lr + half * 32] = a.x;
                sA[lc + 1][lr + half * 32] = a.y;
                sA[lc + 2][lr + half * 32] = a.z;
                sA[lc + 3][lr + half * 32] = a.w;
            }
            float4 b0 = *(const float4*)&Wo[(n0 + lr) * En + k0 + lc];
            float4 b1 = *(const float4*)&Wo[(n0 + lr + 32) * En + k0 + lc];
            sB[lc + 0][lr] = b0.x; sB[lc + 1][lr] = b0.y;
            sB[lc + 2][lr] = b0.z; sB[lc + 3][lr] = b0.w;
            sB[lc + 0][lr + 32] = b1.x; sB[lc + 1][lr + 32] = b1.y;
            sB[lc + 2][lr + 32] = b1.z; sB[lc + 3][lr + 32] = b1.w;
        }
        __syncthreads();

        #pragma unroll
        for (int kk = 0; kk < 32; ++kk) {
            float4 av = *(const float4*)&sA[kk][ty * 4];
            float4 bv = *(const float4*)&sB[kk][tx * 4];
            float a[4] = {av.x, av.y, av.z, av.w};
            float b[4] = {bv.x, bv.y, bv.z, bv.w};
            #pragma unroll
            for (int i = 0; i < 4; ++i)
                #pragma unroll
                for (int j = 0; j < 4; ++j)
                    acc[i][j] += a[i] * b[j];
        }
        __syncthreads();
    }

    #pragma unroll
    for (int i = 0; i < 4; ++i) {
        int m = m0 + ty * 4 + i;
        #pragma unroll
        for (int j = 0; j < 4; ++j) {
            int n = n0 + tx * 4 + j;
            out[m * En + n] = acc[i][j] + bo[n];
        }
    }
}

// ---------------------------------------------------------------------------
extern "C" void kernel_launch(void* const* d_in, const int* in_sizes, int n_in,
                              void* d_out, int out_size)
{
    const float* x  = (const float*)d_in[0];
    const float* Wq = (const float*)d_in[1];
    const float* bq = (const float*)d_in[2];
    const float* Wk = (const float*)d_in[3];
    const float* bk = (const float*)d_in[4];
    const float* Wv = (const float*)d_in[5];
    const float* bv = (const float*)d_in[6];
    const float* Wo = (const float*)d_in[7];
    const float* bo = (const float*)d_in[8];
    float* out = (float*)d_out;

    cudaFuncSetAttribute(attn_kernel,
                         cudaFuncAttributeMaxDynamicSharedMemorySize, SMEM_ATTN);

    dim3 gProj(En / 64, Mtot / 64, 3);
    qkv_proj_kernel<<<gProj, 256>>>(x, Wq, bq, Wk, bk, Wv, bv);

    dim3 gAttn(Sn / 64, BH);
    attn_kernel<<<gAttn, 256, SMEM_ATTN>>>();

    dim3 gOut(En / 64, Mtot / 64);
    out_proj_kernel<<<gOut, 256>>>(Wo, bo, out);
}

// round 3
// speedup vs baseline: 1.1859x; 1.1859x over previous
#include <cuda_runtime.h>

// Problem constants
constexpr int Bn = 4;
constexpr int Sn = 2048;
constexpr int En = 512;
constexpr int Hn = 8;
constexpr int Dn = 64;
constexpr int Mtot = Bn * Sn;   // 8192
constexpr int BH = Bn * Hn;     // 32

constexpr float SCALE = 0.125f;                 // 1/sqrt(64)
constexpr float LOG2_DECAY = -0.07400058144377693f; // log2(0.95)
constexpr float LOG2E = 1.4426950408889634f;

// Scratch (device globals — no allocation allowed)
__device__ float g_q[BH * Sn * Dn];
__device__ float g_k[BH * Sn * Dn];
__device__ float g_v[BH * Sn * Dn];
__device__ float g_attn[BH * Sn * Dn];

// ---------------------------------------------------------------------------
// Kernel 1: fused QKV projection. 128x128x32 tiles, 256 threads, 8x8 micro.
// out[m,n] = sum_k x[m,k] * W[n,k] + b[n], scattered into [B,H,S,D].
// ---------------------------------------------------------------------------
__global__ void __launch_bounds__(256, 2)
qkv_proj_kernel(const float* __restrict__ x,
                const float* __restrict__ Wq, const float* __restrict__ bq,
                const float* __restrict__ Wk, const float* __restrict__ bk,
                const float* __restrict__ Wv, const float* __restrict__ bv)
{
    const float* W;
    const float* bias;
    float* dst;
    if (blockIdx.z == 0)      { W = Wq; bias = bq; dst = g_q; }
    else if (blockIdx.z == 1) { W = Wk; bias = bk; dst = g_k; }
    else                      { W = Wv; bias = bv; dst = g_v; }

    __shared__ float sA[32][132];  // [k][m], padded
    __shared__ float sB[32][132];  // [k][n], padded

    const int tid = threadIdx.x;
    const int tx = tid & 15;
    const int ty = tid >> 4;
    const int m0 = blockIdx.y * 128;
    const int n0 = blockIdx.x * 128;

    float acc[8][8] = {};

    for (int k0 = 0; k0 < En; k0 += 32) {
        // Load A (128x32) and B (128x32), transposed into [k][m]/[k][n]
        #pragma unroll
        for (int u = 0; u < 4; ++u) {
            int idx = tid + u * 256;
            int row = idx >> 3;
            int c4  = (idx & 7) * 4;
            float4 a = *(const float4*)&x[(m0 + row) * En + k0 + c4];
            sA[c4 + 0][row] = a.x; sA[c4 + 1][row] = a.y;
            sA[c4 + 2][row] = a.z; sA[c4 + 3][row] = a.w;
            float4 b = *(const float4*)&W[(n0 + row) * En + k0 + c4];
            sB[c4 + 0][row] = b.x; sB[c4 + 1][row] = b.y;
            sB[c4 + 2][row] = b.z; sB[c4 + 3][row] = b.w;
        }
        __syncthreads();

        #pragma unroll
        for (int kk = 0; kk < 32; ++kk) {
            float4 a0 = *(const float4*)&sA[kk][ty * 4];
            float4 a1 = *(const float4*)&sA[kk][64 + ty * 4];
            float4 b0 = *(const float4*)&sB[kk][tx * 4];
            float4 b1 = *(const float4*)&sB[kk][64 + tx * 4];
            float a[8] = {a0.x, a0.y, a0.z, a0.w, a1.x, a1.y, a1.z, a1.w};
            float b[8] = {b0.x, b0.y, b0.z, b0.w, b1.x, b1.y, b1.z, b1.w};
            #pragma unroll
            for (int i = 0; i < 8; ++i)
                #pragma unroll
                for (int j = 0; j < 8; ++j)
                    acc[i][j] += a[i] * b[j];
        }
        __syncthreads();
    }

    // Epilogue: add bias, scatter into [B,H,S,D]. Split index mapping.
    #pragma unroll
    for (int i = 0; i < 8; ++i) {
        int m = m0 + ((i < 4) ? (ty * 4 + i) : (64 + ty * 4 + i - 4));
        int bb = m >> 11;
        int ss = m & 2047;
        #pragma unroll
        for (int jh = 0; jh < 2; ++jh) {
            int n = n0 + jh * 64 + tx * 4;       // 4 consecutive n, same head
            int hh = n >> 6;
            int dd = n & 63;
            float* p = &dst[(((bb * Hn + hh) * Sn) + ss) * Dn + dd];
            float4 r;
            r.x = acc[i][jh * 4 + 0] + bias[n + 0];
            r.y = acc[i][jh * 4 + 1] + bias[n + 1];
            r.z = acc[i][jh * 4 + 2] + bias[n + 2];
            r.w = acc[i][jh * 4 + 3] + bias[n + 3];
            *(float4*)p = r;
        }
    }
}

// ---------------------------------------------------------------------------
// Kernel 2: flash-style attention with decay mask.
// CTA = (bh, 128-query tile); key tiles of 64. 256 threads.
// Microtile: 8 query rows (split ty*4 / 64+ty*4) x 4 keys (tx*4).
// ---------------------------------------------------------------------------
constexpr int SMEM_ATTN = (64 * 132 + 64 * 68 + 64 * 68 + 128 * 68) * 4; // 103424 B

__global__ void __launch_bounds__(256, 2)
attn_kernel()
{
    extern __shared__ float sm[];
    float (*sQ)[132] = (float(*)[132])(sm);                         // [d][i]
    float (*sK)[68]  = (float(*)[68])(sm + 64 * 132);               // [d][j]
    float (*sV)[68]  = (float(*)[68])(sm + 64 * 132 + 64 * 68);     // [j][d]
    float (*sP)[68]  = (float(*)[68])(sm + 64 * 132 + 2 * 64 * 68); // [i][j]

    const int bh = blockIdx.y;
    const int q0 = blockIdx.x * 128;
    const float* Q = g_q + bh * Sn * Dn;
    const float* K = g_k + bh * Sn * Dn;
    const float* V = g_v + bh * Sn * Dn;
    float* O = g_attn + bh * Sn * Dn;

    const int tid = threadIdx.x;
    const int tx = tid & 15;
    const int ty = tid >> 4;

    // Row indices for this thread's 8 query rows (within tile)
    int ir[8];
    #pragma unroll
    for (int i = 0; i < 4; ++i) { ir[i] = ty * 4 + i; ir[i + 4] = 64 + ty * 4 + i; }

    // Load Q tile (128 rows x 64 d), scaled, transposed into sQ[d][i]
    #pragma unroll
    for (int u = 0; u < 8; ++u) {
        int idx = tid + u * 256;
        int row = idx >> 4;
        int c4  = (idx & 15) * 4;
        float4 q = *(const float4*)&Q[(q0 + row) * Dn + c4];
        sQ[c4 + 0][row] = q.x * SCALE;
        sQ[c4 + 1][row] = q.y * SCALE;
        sQ[c4 + 2][row] = q.z * SCALE;
        sQ[c4 + 3][row] = q.w * SCALE;
    }

    float m_i[8], l_i[8], o[8][4];
    #pragma unroll
    for (int i = 0; i < 8; ++i) {
        m_i[i] = -1e30f;
        l_i[i] = 0.f;
        #pragma unroll
        for (int j = 0; j < 4; ++j) o[i][j] = 0.f;
    }

    for (int kt = 0; kt < Sn / 64; ++kt) {
        const int k0 = kt * 64;
        __syncthreads();  // prior PV readers of sK/sV/sP done; Q stores visible (iter 0)

        // Load K (transposed) and V tiles (64x64 each) — FULL 64 rows
        #pragma unroll
        for (int u = 0; u < 4; ++u) {
            int idx = tid + u * 256;
            int row = idx >> 4;          // 0..63
            int c4  = (idx & 15) * 4;    // 0..60
            float4 kv = *(const float4*)&K[(k0 + row) * Dn + c4];
            sK[c4 + 0][row] = kv.x; sK[c4 + 1][row] = kv.y;
            sK[c4 + 2][row] = kv.z; sK[c4 + 3][row] = kv.w;
            float4 vv = *(const float4*)&V[(k0 + row) * Dn + c4];
            *(float4*)&sV[row][c4] = vv;
        }
        __syncthreads();

        // Scores: s[i][j] = sum_d Qs[i][d] K[j][d]
        float s[8][4] = {};
        #pragma unroll 16
        for (int d = 0; d < 64; ++d) {
            float4 a0 = *(const float4*)&sQ[d][ty * 4];
            float4 a1 = *(const float4*)&sQ[d][64 + ty * 4];
            float4 bv = *(const float4*)&sK[d][tx * 4];
            float a[8] = {a0.x, a0.y, a0.z, a0.w, a1.x, a1.y, a1.z, a1.w};
            float b[4] = {bv.x, bv.y, bv.z, bv.w};
            #pragma unroll
            for (int i = 0; i < 8; ++i)
                #pragma unroll
                for (int j = 0; j < 4; ++j)
                    s[i][j] += a[i] * b[j];
        }

        // Decay mask
        #pragma unroll
        for (int i = 0; i < 8; ++i) {
            int gi = q0 + ir[i];
            #pragma unroll
            for (int j = 0; j < 4; ++j) {
                int gj = k0 + tx * 4 + j;
                int dif = gi - gj;
                if (dif < 0) dif = -dif;
                s[i][j] *= exp2f(LOG2_DECAY * (float)dif);
            }
        }

        // Online softmax (row = 16 lanes sharing ty)
        #pragma unroll
        for (int i = 0; i < 8; ++i) {
            float mv = fmaxf(fmaxf(s[i][0], s[i][1]), fmaxf(s[i][2], s[i][3]));
            #pragma unroll
            for (int off = 8; off > 0; off >>= 1)
                mv = fmaxf(mv, __shfl_xor_sync(0xffffffffu, mv, off, 16));
            float mn = fmaxf(m_i[i], mv);
            float corr = exp2f((m_i[i] - mn) * LOG2E);
            m_i[i] = mn;
            l_i[i] *= corr;
            #pragma unroll
            for (int j = 0; j < 4; ++j) o[i][j] *= corr;
            float r = 0.f;
            #pragma unroll
            for (int j = 0; j < 4; ++j) {
                float p = exp2f((s[i][j] - mn) * LOG2E);
                s[i][j] = p;
                r += p;
            }
            #pragma unroll
            for (int off = 8; off > 0; off >>= 1)
                r += __shfl_xor_sync(0xffffffffu, r, off, 16);
            l_i[i] += r;
        }

        // Write P into sP[i][j]
        #pragma unroll
        for (int i = 0; i < 8; ++i)
            *(float4*)&sP[ir[i]][tx * 4] =
                make_float4(s[i][0], s[i][1], s[i][2], s[i][3]);
        __syncthreads();

        // O += P @ V   (o[i][d], d = tx*4..tx*4+3)
        #pragma unroll 8
        for (int j = 0; j < 64; ++j) {
            float4 vv = *(const float4*)&sV[j][tx * 4];
            float p[8];
            #pragma unroll
            for (int i = 0; i < 8; ++i) p[i] = sP[ir[i]][j];
            #pragma unroll
            for (int i = 0; i < 8; ++i) {
                o[i][0] += p[i] * vv.x;
                o[i][1] += p[i] * vv.y;
                o[i][2] += p[i] * vv.z;
                o[i][3] += p[i] * vv.w;
            }
        }
    }

    // Epilogue: normalize and store
    #pragma unroll
    for (int i = 0; i < 8; ++i) {
        float inv = 1.0f / l_i[i];
        int row = q0 + ir[i];
        float4 res = make_float4(o[i][0] * inv, o[i][1] * inv,
                                 o[i][2] * inv, o[i][3] * inv);
        *(float4*)&O[row * Dn + tx * 4] = res;
    }
}

// ---------------------------------------------------------------------------
// Kernel 3: output projection. Same tiling; A gathered from [B,H,S,D].
// ---------------------------------------------------------------------------
__global__ void __launch_bounds__(256, 2)
out_proj_kernel(const float* __restrict__ Wo, const float* __restrict__ bo,
                float* __restrict__ out)
{
    __shared__ float sA[32][132];
    __shared__ float sB[32][132];

    const int tid = threadIdx.x;
    const int tx = tid & 15;
    const int ty = tid >> 4;
    const int m0 = blockIdx.y * 128;
    const int n0 = blockIdx.x * 128;

    float acc[8][8] = {};

    for (int k0 = 0; k0 < En; k0 += 32) {
        #pragma unroll
        for (int u = 0; u < 4; ++u) {
            int idx = tid + u * 256;
            int row = idx >> 3;
            int c4  = (idx & 7) * 4;
            // Gather A[m][k] from g_attn[b][h][s][d]
            int m = m0 + row;
            int bb = m >> 11;
            int ss = m & 2047;
            int k = k0 + c4;
            int hh = k >> 6;
            int dd = k & 63;
            float4 a = *(const float4*)&g_attn[(((bb * Hn + hh) * Sn) + ss) * Dn + dd];
            sA[c4 + 0][row] = a.x; sA[c4 + 1][row] = a.y;
            sA[c4 + 2][row] = a.z; sA[c4 + 3][row] = a.w;
            float4 b = *(const float4*)&Wo[(n0 + row) * En + k0 + c4];
            sB[c4 + 0][row] = b.x; sB[c4 + 1][row] = b.y;
            sB[c4 + 2][row] = b.z; sB[c4 + 3][row] = b.w;
        }
        __syncthreads();

        #pragma unroll
        for (int kk = 0; kk < 32; ++kk) {
            float4 a0 = *(const float4*)&sA[kk][ty * 4];
            float4 a1 = *(const float4*)&sA[kk][64 + ty * 4];
            float4 b0 = *(const float4*)&sB[kk][tx * 4];
            float4 b1 = *(const float4*)&sB[kk][64 + tx * 4];
            float a[8] = {a0.x, a0.y, a0.z, a0.w, a1.x, a1.y, a1.z, a1.w};
            float b[8] = {b0.x, b0.y, b0.z, b0.w, b1.x, b1.y, b1.z, b1.w};
            #pragma unroll
            for (int i = 0; i < 8; ++i)
                #pragma unroll
                for (int j = 0; j < 8; ++j)
                    acc[i][j] += a[i] * b[j];
        }
        __syncthreads();
    }

    #pragma unroll
    for (int i = 0; i < 8; ++i) {
        int m = m0 + ((i < 4) ? (ty * 4 + i) : (64 + ty * 4 + i - 4));
        #pragma unroll
        for (int jh = 0; jh < 2; ++jh) {
            int n = n0 + jh * 64 + tx * 4;
            float4 r;
            r.x = acc[i][jh * 4 + 0] + bo[n + 0];
            r.y = acc[i][jh * 4 + 1] + bo[n + 1];
            r.z = acc[i][jh * 4 + 2] + bo[n + 2];
            r.w = acc[i][jh * 4 + 3] + bo[n + 3];
            *(float4*)&out[m * En + n] = r;
        }
    }
}

// ---------------------------------------------------------------------------
extern "C" void kernel_launch(void* const* d_in, const int* in_sizes, int n_in,
                              void* d_out, int out_size)
{
    const float* x  = (const float*)d_in[0];
    const float* Wq = (const float*)d_in[1];
    const float* bq = (const float*)d_in[2];
    const float* Wk = (const float*)d_in[3];
    const float* bk = (const float*)d_in[4];
    const float* Wv = (const float*)d_in[5];
    const float* bv = (const float*)d_in[6];
    const float* Wo = (const float*)d_in[7];
    const float* bo = (const float*)d_in[8];
    float* out = (float*)d_out;

    cudaFuncSetAttribute(attn_kernel,
                         cudaFuncAttributeMaxDynamicSharedMemorySize, SMEM_ATTN);

    dim3 gProj(En / 128, Mtot / 128, 3);
    qkv_proj_kernel<<<gProj, 256>>>(x, Wq, bq, Wk, bk, Wv, bv);

    dim3 gAttn(Sn / 128, BH);
    attn_kernel<<<gAttn, 256, SMEM_ATTN>>>();

    dim3 gOut(En / 128, Mtot / 128);
    out_proj_kernel<<<gOut, 256>>>(Wo, bo, out);
}

// round 6
// speedup vs baseline: 1.4217x; 1.1989x over previous
#include <cuda_runtime.h>
#include <cuda_bf16.h>
#include <cstdint>

// Problem constants
constexpr int Bn = 4;
constexpr int Sn = 2048;
constexpr int En = 512;
constexpr int Hn = 8;
constexpr int Dn = 64;
constexpr int Mtot = Bn * Sn;   // 8192
constexpr int BH = Bn * Hn;     // 32

constexpr float SCALE = 0.125f;                 // 1/sqrt(64)
constexpr float LOG2_DECAY = -0.07400058144377693f; // log2(0.95)
constexpr float LOG2E = 1.4426950408889634f;

// ---------------------------------------------------------------------------
// Scratch (device globals — no allocation allowed)
// ---------------------------------------------------------------------------
__device__ float g_q[BH * Sn * Dn];
__device__ float g_k[BH * Sn * Dn];
__device__ float g_v[BH * Sn * Dn];
__device__ float g_attn[BH * Sn * Dn];

// split-bf16 operands
__device__ __nv_bfloat16 g_xh[Mtot * En];
__device__ __nv_bfloat16 g_xl[Mtot * En];
__device__ __nv_bfloat16 g_wh[4 * En * En];   // slots: Wq, Wk, Wv, Wo
__device__ __nv_bfloat16 g_wl[4 * En * En];
__device__ __nv_bfloat16 g_ah[Mtot * En];     // attention output, [m][k] gathered
__device__ __nv_bfloat16 g_al[Mtot * En];

// ---------------------------------------------------------------------------
// mma.sync helpers (sm_80+, compiles under compute_100)
// ---------------------------------------------------------------------------
__device__ __forceinline__ uint32_t smem_u32(const void* p) {
    uint32_t a;
    asm("{ .reg .u64 t; cvta.to.shared.u64 t, %1; cvt.u32.u64 %0, t; }"
        : "=r"(a) : "l"(p));
    return a;
}

__device__ __forceinline__ void ldm_x4(uint32_t addr, uint32_t* r) {
    asm volatile("ldmatrix.sync.aligned.m8n8.x4.shared.b16 {%0,%1,%2,%3}, [%4];"
                 : "=r"(r[0]), "=r"(r[1]), "=r"(r[2]), "=r"(r[3]) : "r"(addr));
}

__device__ __forceinline__ void mma16816(float* c, const uint32_t* a, const uint32_t* b) {
    asm volatile(
        "mma.sync.aligned.m16n8k16.row.col.f32.bf16.bf16.f32 "
        "{%0,%1,%2,%3}, {%4,%5,%6,%7}, {%8,%9}, {%0,%1,%2,%3};"
        : "+f"(c[0]), "+f"(c[1]), "+f"(c[2]), "+f"(c[3])
        : "r"(a[0]), "r"(a[1]), "r"(a[2]), "r"(a[3]), "r"(b[0]), "r"(b[1]));
}

// ---------------------------------------------------------------------------
// Conversion kernels: fp32 -> (hi, lo) bf16 pair
// ---------------------------------------------------------------------------
__global__ void convert_split(const float* __restrict__ src, int which, int n)
{
    __nv_bfloat16 *hi, *lo;
    if (which == 0) { hi = g_xh; lo = g_xl; }
    else { hi = g_wh + (which - 1) * En * En; lo = g_wl + (which - 1) * En * En; }
    for (int i = blockIdx.x * blockDim.x + threadIdx.x; i < n;
         i += gridDim.x * blockDim.x) {
        float v = src[i];
        __nv_bfloat16 h = __float2bfloat16(v);
        float r = v - __bfloat162float(h);
        hi[i] = h;
        lo[i] = __float2bfloat16(r);
    }
}

// Gather g_attn [B,H,S,D] into flat [m][k] and split
__global__ void convert_attn()
{
    const int n = Mtot * En;
    for (int i = blockIdx.x * blockDim.x + threadIdx.x; i < n;
         i += gridDim.x * blockDim.x) {
        int m = i >> 9;
        int k = i & 511;
        int b = m >> 11, s = m & 2047, h = k >> 6, d = k & 63;
        float v = g_attn[((b * Hn + h) * Sn + s) * Dn + d];
        __nv_bfloat16 hh = __float2bfloat16(v);
        float r = v - __bfloat162float(hh);
        g_ah[i] = hh;
        g_al[i] = __float2bfloat16(r);
    }
}

// ---------------------------------------------------------------------------
// mma.sync split-bf16 GEMM: C[128x128] = A[128x512] * B[512x128]^T + bias
//   3-pass: Ah*Bh + Al*Bh + Ah*Bl, fp32 accum in registers.
//   which 0/1/2: A = x, B = W{q,k,v}; epilogue scatters to g_q/g_k/g_v [B,H,S,D]
//   which 3:     A = attn_flat, B = Wo; epilogue writes out [M,E]
// 256 threads = 8 warps (4 along m x 2 along n); warp tile 32m x 64n.
// ---------------------------------------------------------------------------
constexpr int TP = 72;                 // smem tile pitch in bf16 (144 B/row)
constexpr int TILE_ELE = 128 * TP;     // 9216 bf16 per tile
constexpr int GE_SMEM = 4 * TILE_ELE * 2;  // 73728 B

__global__ void __launch_bounds__(256, 2)
gemm_mma(const float* __restrict__ bq, const float* __restrict__ bk,
         const float* __restrict__ bv, const float* __restrict__ bo,
         float* __restrict__ out, int which_arg)
{
    extern __shared__ __nv_bfloat16 smb[];
    __nv_bfloat16* sAh = smb;
    __nv_bfloat16* sAl = sAh + TILE_ELE;
    __nv_bfloat16* sBh = sAl + TILE_ELE;
    __nv_bfloat16* sBl = sBh + TILE_ELE;

    const int tid  = threadIdx.x;
    const int lane = tid & 31;
    const int wid  = tid >> 5;
    const int which = (which_arg < 0) ? (int)blockIdx.z : which_arg;

    const __nv_bfloat16* Ah = (which < 3) ? g_xh : g_ah;
    const __nv_bfloat16* Al = (which < 3) ? g_xl : g_al;
    const __nv_bfloat16* Bh = g_wh + which * En * En;
    const __nv_bfloat16* Bl = g_wl + which * En * En;
    const float* bias = (which == 0) ? bq : (which == 1) ? bk :
                        (which == 2) ? bv : bo;

    const int n0 = blockIdx.x * 128;
    const int m0 = blockIdx.y * 128;
    const int wm = (wid & 3) * 32;   // warp m offset (4 warps along m)
    const int wn = (wid >> 2) * 64;  // warp n offset (2 warps along n)

    // ldmatrix per-lane offsets (bytes) within a tile
    const int g = lane >> 3, r = lane & 7;
    const uint32_t aoff = (uint32_t)((((g & 1) * 8 + r) * TP + (g >> 1) * 8) * 2);
    const uint32_t boff = (uint32_t)((((g >> 1) * 8 + r) * TP + (g & 1) * 8) * 2);
    const uint32_t uAh = smem_u32(sAh), uAl = smem_u32(sAl);
    const uint32_t uBh = smem_u32(sBh), uBl = smem_u32(sBl);

    float acc[2][8][4] = {};

    for (int kc = 0; kc < 8; ++kc) {      // k-chunks of 64
        // ---- load 4 tiles (128 rows x 64 bf16) into padded smem ----
        {
            const __nv_bfloat16* srcs[4] = {Ah, Al, Bh, Bl};
            __nv_bfloat16* dsts[4] = {sAh, sAl, sBh, sBl};
            const int rbs[4] = {m0, m0, n0, n0};
            #pragma unroll
            for (int t = 0; t < 4; ++t) {
                #pragma unroll
                for (int p = 0; p < 4; ++p) {
                    int seg = tid + p * 256;      // 0..1023
                    int row = seg >> 3;           // 0..127
                    int c16 = seg & 7;            // 16B segment
                    uint4 v = *(const uint4*)&srcs[t][(rbs[t] + row) * En + kc * 64 + c16 * 8];
                    *(uint4*)&dsts[t][row * TP + c16 * 8] = v;
                }
            }
        }
        __syncthreads();

        #pragma unroll
        for (int ks = 0; ks < 4; ++ks) {  // k16 steps within chunk
            const uint32_t kb = (uint32_t)(ks * 16 * 2);  // byte offset along k
            uint32_t ah[2][4], al[2][4], bb[8][2];

            // A-hi fragments (2 m16 tiles)
            #pragma unroll
            for (int mt = 0; mt < 2; ++mt)
                ldm_x4(uAh + (uint32_t)((wm + mt * 16) * TP * 2) + kb + aoff, ah[mt]);
            // B-hi fragments (8 n8 tiles via 4 x4-ldmatrix)
            #pragma unroll
            for (int t2 = 0; t2 < 4; ++t2) {
                uint32_t q[4];
                ldm_x4(uBh + (uint32_t)((wn + t2 * 16) * TP * 2) + kb + boff, q);
                bb[2 * t2][0] = q[0]; bb[2 * t2][1] = q[1];
                bb[2 * t2 + 1][0] = q[2]; bb[2 * t2 + 1][1] = q[3];
            }
            // pass 1: Ah * Bh
            #pragma unroll
            for (int mt = 0; mt < 2; ++mt)
                #pragma unroll
                for (int nt = 0; nt < 8; ++nt)
                    mma16816(acc[mt][nt], ah[mt], bb[nt]);

            // A-lo fragments, pass 2: Al * Bh
            #pragma unroll
            for (int mt = 0; mt < 2; ++mt)
                ldm_x4(uAl + (uint32_t)((wm + mt * 16) * TP * 2) + kb + aoff, al[mt]);
            #pragma unroll
            for (int mt = 0; mt < 2; ++mt)
                #pragma unroll
                for (int nt = 0; nt < 8; ++nt)
                    mma16816(acc[mt][nt], al[mt], bb[nt]);

            // B-lo fragments (reuse bb regs), pass 3: Ah * Bl
            #pragma unroll
            for (int t2 = 0; t2 < 4; ++t2) {
                uint32_t q[4];
                ldm_x4(uBl + (uint32_t)((wn + t2 * 16) * TP * 2) + kb + boff, q);
                bb[2 * t2][0] = q[0]; bb[2 * t2][1] = q[1];
                bb[2 * t2 + 1][0] = q[2]; bb[2 * t2 + 1][1] = q[3];
            }
            #pragma unroll
            for (int mt = 0; mt < 2; ++mt)
                #pragma unroll
                for (int nt = 0; nt < 8; ++nt)
                    mma16816(acc[mt][nt], ah[mt], bb[nt]);
        }
        __syncthreads();
    }

    // ---- epilogue: bias + store ----
    float* dstq = (which == 0) ? g_q : (which == 1) ? g_k : g_v;
    #pragma unroll
    for (int mt = 0; mt < 2; ++mt) {
        #pragma unroll
        for (int nt = 0; nt < 8; ++nt) {
            int m = m0 + wm + mt * 16 + (lane >> 2);
            int n = n0 + wn + nt * 8 + (lane & 3) * 2;
            float bx = bias[n], by = bias[n + 1];
            float2 v0 = make_float2(acc[mt][nt][0] + bx, acc[mt][nt][1] + by);
            float2 v1 = make_float2(acc[mt][nt][2] + bx, acc[mt][nt][3] + by);
            if (which < 3) {
                int h = n >> 6, d = n & 63;
                int b0i = m >> 11, s0 = m & 2047;
                int m1 = m + 8;
                int b1i = m1 >> 11, s1 = m1 & 2047;
                *(float2*)&dstq[((b0i * Hn + h) * Sn + s0) * Dn + d] = v0;
                *(float2*)&dstq[((b1i * Hn + h) * Sn + s1) * Dn + d] = v1;
            } else {
                *(float2*)&out[m * En + n] = v0;
                *(float2*)&out[(m + 8) * En + n] = v1;
            }
        }
    }
}

// ---------------------------------------------------------------------------
// Kernel 2: flash-style attention with decay mask (unchanged, known-good R3).
// ---------------------------------------------------------------------------
constexpr int SMEM_ATTN = (64 * 132 + 64 * 68 + 64 * 68 + 128 * 68) * 4; // 103424 B

__global__ void __launch_bounds__(256, 2)
attn_kernel()
{
    extern __shared__ float sm[];
    float (*sQ)[132] = (float(*)[132])(sm);                         // [d][i]
    float (*sK)[68]  = (float(*)[68])(sm + 64 * 132);               // [d][j]
    float (*sV)[68]  = (float(*)[68])(sm + 64 * 132 + 64 * 68);     // [j][d]
    float (*sP)[68]  = (float(*)[68])(sm + 64 * 132 + 2 * 64 * 68); // [i][j]

    const int bh = blockIdx.y;
    const int q0 = blockIdx.x * 128;
    const float* Q = g_q + bh * Sn * Dn;
    const float* K = g_k + bh * Sn * Dn;
    const float* V = g_v + bh * Sn * Dn;
    float* O = g_attn + bh * Sn * Dn;

    const int tid = threadIdx.x;
    const int tx = tid & 15;
    const int ty = tid >> 4;

    int ir[8];
    #pragma unroll
    for (int i = 0; i < 4; ++i) { ir[i] = ty * 4 + i; ir[i + 4] = 64 + ty * 4 + i; }

    #pragma unroll
    for (int u = 0; u < 8; ++u) {
        int idx = tid + u * 256;
        int row = idx >> 4;
        int c4  = (idx & 15) * 4;
        float4 q = *(const float4*)&Q[(q0 + row) * Dn + c4];
        sQ[c4 + 0][row] = q.x * SCALE;
        sQ[c4 + 1][row] = q.y * SCALE;
        sQ[c4 + 2][row] = q.z * SCALE;
        sQ[c4 + 3][row] = q.w * SCALE;
    }

    float m_i[8], l_i[8], o[8][4];
    #pragma unroll
    for (int i = 0; i < 8; ++i) {
        m_i[i] = -1e30f;
        l_i[i] = 0.f;
        #pragma unroll
        for (int j = 0; j < 4; ++j) o[i][j] = 0.f;
    }

    for (int kt = 0; kt < Sn / 64; ++kt) {
        const int k0 = kt * 64;
        __syncthreads();

        #pragma unroll
        for (int u = 0; u < 4; ++u) {
            int idx = tid + u * 256;
            int row = idx >> 4;          // 0..63
            int c4  = (idx & 15) * 4;    // 0..60
            float4 kv = *(const float4*)&K[(k0 + row) * Dn + c4];
            sK[c4 + 0][row] = kv.x; sK[c4 + 1][row] = kv.y;
            sK[c4 + 2][row] = kv.z; sK[c4 + 3][row] = kv.w;
            float4 vv = *(const float4*)&V[(k0 + row) * Dn + c4];
            *(float4*)&sV[row][c4] = vv;
        }
        __syncthreads();

        float s[8][4] = {};
        #pragma unroll 16
        for (int d = 0; d < 64; ++d) {
            float4 a0 = *(const float4*)&sQ[d][ty * 4];
            float4 a1 = *(const float4*)&sQ[d][64 + ty * 4];
            float4 bv = *(const float4*)&sK[d][tx * 4];
            float a[8] = {a0.x, a0.y, a0.z, a0.w, a1.x, a1.y, a1.z, a1.w};
            float b[4] = {bv.x, bv.y, bv.z, bv.w};
            #pragma unroll
            for (int i = 0; i < 8; ++i)
                #pragma unroll
                for (int j = 0; j < 4; ++j)
                    s[i][j] += a[i] * b[j];
        }

        #pragma unroll
        for (int i = 0; i < 8; ++i) {
            int gi = q0 + ir[i];
            #pragma unroll
            for (int j = 0; j < 4; ++j) {
                int gj = k0 + tx * 4 + j;
                int dif = gi - gj;
                if (dif < 0) dif = -dif;
                s[i][j] *= exp2f(LOG2_DECAY * (float)dif);
            }
        }

        #pragma unroll
        for (int i = 0; i < 8; ++i) {
            float mv = fmaxf(fmaxf(s[i][0], s[i][1]), fmaxf(s[i][2], s[i][3]));
            #pragma unroll
            for (int off = 8; off > 0; off >>= 1)
                mv = fmaxf(mv, __shfl_xor_sync(0xffffffffu, mv, off, 16));
            float mn = fmaxf(m_i[i], mv);
            float corr = exp2f((m_i[i] - mn) * LOG2E);
            m_i[i] = mn;
            l_i[i] *= corr;
            #pragma unroll
            for (int j = 0; j < 4; ++j) o[i][j] *= corr;
            float r = 0.f;
            #pragma unroll
            for (int j = 0; j < 4; ++j) {
                float p = exp2f((s[i][j] - mn) * LOG2E);
                s[i][j] = p;
                r += p;
            }
            #pragma unroll
            for (int off = 8; off > 0; off >>= 1)
                r += __shfl_xor_sync(0xffffffffu, r, off, 16);
            l_i[i] += r;
        }

        #pragma unroll
        for (int i = 0; i < 8; ++i)
            *(float4*)&sP[ir[i]][tx * 4] =
                make_float4(s[i][0], s[i][1], s[i][2], s[i][3]);
        __syncthreads();

        #pragma unroll 8
        for (int j = 0; j < 64; ++j) {
            float4 vv = *(const float4*)&sV[j][tx * 4];
            float p[8];
            #pragma unroll
            for (int i = 0; i < 8; ++i) p[i] = sP[ir[i]][j];
            #pragma unroll
            for (int i = 0; i < 8; ++i) {
                o[i][0] += p[i] * vv.x;
                o[i][1] += p[i] * vv.y;
                o[i][2] += p[i] * vv.z;
                o[i][3] += p[i] * vv.w;
            }
        }
    }

    #pragma unroll
    for (int i = 0; i < 8; ++i) {
        float inv = 1.0f / l_i[i];
        int row = q0 + ir[i];
        float4 res = make_float4(o[i][0] * inv, o[i][1] * inv,
                                 o[i][2] * inv, o[i][3] * inv);
        *(float4*)&O[row * Dn + tx * 4] = res;
    }
}

// ---------------------------------------------------------------------------
extern "C" void kernel_launch(void* const* d_in, const int* in_sizes, int n_in,
                              void* d_out, int out_size)
{
    const float* x  = (const float*)d_in[0];
    const float* Wq = (const float*)d_in[1];
    const float* bq = (const float*)d_in[2];
    const float* Wk = (const float*)d_in[3];
    const float* bk = (const float*)d_in[4];
    const float* Wv = (const float*)d_in[5];
    const float* bv = (const float*)d_in[6];
    const float* Wo = (const float*)d_in[7];
    const float* bo = (const float*)d_in[8];
    float* out = (float*)d_out;

    cudaFuncSetAttribute(gemm_mma,
                         cudaFuncAttributeMaxDynamicSharedMemorySize, GE_SMEM);
    cudaFuncSetAttribute(attn_kernel,
                         cudaFuncAttributeMaxDynamicSharedMemorySize, SMEM_ATTN);

    // Split-precision conversions
    convert_split<<<2048, 256>>>(x,  0, Mtot * En);
    convert_split<<<512,  256>>>(Wq, 1, En * En);
    convert_split<<<512,  256>>>(Wk, 2, En * En);
    convert_split<<<512,  256>>>(Wv, 3, En * En);
    convert_split<<<512,  256>>>(Wo, 4, En * En);

    // QKV projections (tensor cores, mma.sync)
    dim3 gQKV(En / 128, Mtot / 128, 3);
    gemm_mma<<<gQKV, 256, GE_SMEM>>>(bq, bk, bv, bo, out, -1);

    // Attention (SIMT, unchanged)
    dim3 gAttn(Sn / 128, BH);
    attn_kernel<<<gAttn, 256, SMEM_ATTN>>>();

    // Gather+split attention output, then output projection
    convert_attn<<<2048, 256>>>();
    dim3 gOut(En / 128, Mtot / 128, 1);
    gemm_mma<<<gOut, 256, GE_SMEM>>>(bq, bk, bv, bo, out, 3);
}

// round 7
// speedup vs baseline: 3.0920x; 2.1748x over previous
#include <cuda_runtime.h>
#include <cuda_bf16.h>
#include <cstdint>

// Problem constants
constexpr int Bn = 4;
constexpr int Sn = 2048;
constexpr int En = 512;
constexpr int Hn = 8;
constexpr int Dn = 64;
constexpr int Mtot = Bn * Sn;   // 8192
constexpr int BH = Bn * Hn;     // 32

constexpr float SCALE = 0.125f;                 // 1/sqrt(64)
constexpr float LOG2_DECAY = -0.07400058144377693f; // log2(0.95)
constexpr float LOG2E = 1.4426950408889634f;

// ---------------------------------------------------------------------------
// Scratch (device globals — no allocation allowed)
// ---------------------------------------------------------------------------
// split-bf16 operands for projections
__device__ __nv_bfloat16 g_xh[Mtot * En];
__device__ __nv_bfloat16 g_xl[Mtot * En];
__device__ __nv_bfloat16 g_wh[4 * En * En];   // slots: Wq, Wk, Wv, Wo
__device__ __nv_bfloat16 g_wl[4 * En * En];

// split-bf16 Q (pre-scaled), K: [B,H,S,D]; V transposed: [B,H,D,S]
__device__ __nv_bfloat16 g_qh[BH * Sn * Dn];
__device__ __nv_bfloat16 g_ql[BH * Sn * Dn];
__device__ __nv_bfloat16 g_kh[BH * Sn * Dn];
__device__ __nv_bfloat16 g_kl[BH * Sn * Dn];
__device__ __nv_bfloat16 g_vth[BH * Sn * Dn];
__device__ __nv_bfloat16 g_vtl[BH * Sn * Dn];

// attention output, flat [m][k] (k = h*64+d), split
__device__ __nv_bfloat16 g_ah[Mtot * En];
__device__ __nv_bfloat16 g_al[Mtot * En];

// ---------------------------------------------------------------------------
// mma.sync helpers
// ---------------------------------------------------------------------------
__device__ __forceinline__ uint32_t smem_u32(const void* p) {
    uint32_t a;
    asm("{ .reg .u64 t; cvta.to.shared.u64 t, %1; cvt.u32.u64 %0, t; }"
        : "=r"(a) : "l"(p));
    return a;
}

__device__ __forceinline__ void ldm_x4(uint32_t addr, uint32_t* r) {
    asm volatile("ldmatrix.sync.aligned.m8n8.x4.shared.b16 {%0,%1,%2,%3}, [%4];"
                 : "=r"(r[0]), "=r"(r[1]), "=r"(r[2]), "=r"(r[3]) : "r"(addr));
}

__device__ __forceinline__ void mma16816(float* c, const uint32_t* a, const uint32_t* b) {
    asm volatile(
        "mma.sync.aligned.m16n8k16.row.col.f32.bf16.bf16.f32 "
        "{%0,%1,%2,%3}, {%4,%5,%6,%7}, {%8,%9}, {%0,%1,%2,%3};"
        : "+f"(c[0]), "+f"(c[1]), "+f"(c[2]), "+f"(c[3])
        : "r"(a[0]), "r"(a[1]), "r"(a[2]), "r"(a[3]), "r"(b[0]), "r"(b[1]));
}

__device__ __forceinline__ uint32_t packbf(float e0, float e1) {
    __nv_bfloat162 h = __floats2bfloat162_rn(e0, e1);   // .x = e0 (low)
    return *(uint32_t*)&h;
}

// ---------------------------------------------------------------------------
// Conversion kernels: fp32 -> (hi, lo) bf16 pair
// ---------------------------------------------------------------------------
__global__ void convert_split(const float* __restrict__ src, int which, int n)
{
    __nv_bfloat16 *hi, *lo;
    if (which == 0) { hi = g_xh; lo = g_xl; }
    else { hi = g_wh + (which - 1) * En * En; lo = g_wl + (which - 1) * En * En; }
    for (int i = blockIdx.x * blockDim.x + threadIdx.x; i < n;
         i += gridDim.x * blockDim.x) {
        float v = src[i];
        __nv_bfloat16 h = __float2bfloat16(v);
        float r = v - __bfloat162float(h);
        hi[i] = h;
        lo[i] = __float2bfloat16(r);
    }
}

// ---------------------------------------------------------------------------
// mma.sync split-bf16 GEMM: C[128x128] = A[128x512] * B[512x128]^T + bias
//   which 0: -> split Q (x SCALE) [B,H,S,D]
//   which 1: -> split K [B,H,S,D]
//   which 2: -> split V^T [B,H,D,S]
//   which 3: A = attn_flat, B = Wo; epilogue writes fp32 out [M,E]
// 256 threads = 8 warps (4 along m x 2 along n); warp tile 32m x 64n.
// ---------------------------------------------------------------------------
constexpr int TP = 72;                 // smem tile pitch in bf16 (144 B/row)
constexpr int TILE_ELE = 128 * TP;     // 9216 bf16 per tile
constexpr int GE_SMEM = 4 * TILE_ELE * 2;  // 73728 B

__global__ void __launch_bounds__(256, 2)
gemm_mma(const float* __restrict__ bq, const float* __restrict__ bk,
         const float* __restrict__ bv, const float* __restrict__ bo,
         float* __restrict__ out, int which_arg)
{
    extern __shared__ __nv_bfloat16 smb[];
    __nv_bfloat16* sAh = smb;
    __nv_bfloat16* sAl = sAh + TILE_ELE;
    __nv_bfloat16* sBh = sAl + TILE_ELE;
    __nv_bfloat16* sBl = sBh + TILE_ELE;

    const int tid  = threadIdx.x;
    const int lane = tid & 31;
    const int wid  = tid >> 5;
    const int which = (which_arg < 0) ? (int)blockIdx.z : which_arg;

    const __nv_bfloat16* Ah = (which < 3) ? g_xh : g_ah;
    const __nv_bfloat16* Al = (which < 3) ? g_xl : g_al;
    const __nv_bfloat16* Bh = g_wh + which * En * En;
    const __nv_bfloat16* Bl = g_wl + which * En * En;
    const float* bias = (which == 0) ? bq : (which == 1) ? bk :
                        (which == 2) ? bv : bo;

    const int n0 = blockIdx.x * 128;
    const int m0 = blockIdx.y * 128;
    const int wm = (wid & 3) * 32;
    const int wn = (wid >> 2) * 64;

    const int g = lane >> 3, r = lane & 7;
    const uint32_t aoff = (uint32_t)((((g & 1) * 8 + r) * TP + (g >> 1) * 8) * 2);
    const uint32_t boff = (uint32_t)((((g >> 1) * 8 + r) * TP + (g & 1) * 8) * 2);
    const uint32_t uAh = smem_u32(sAh), uAl = smem_u32(sAl);
    const uint32_t uBh = smem_u32(sBh), uBl = smem_u32(sBl);

    float acc[2][8][4] = {};

    for (int kc = 0; kc < 8; ++kc) {
        {
            const __nv_bfloat16* srcs[4] = {Ah, Al, Bh, Bl};
            __nv_bfloat16* dsts[4] = {sAh, sAl, sBh, sBl};
            const int rbs[4] = {m0, m0, n0, n0};
            #pragma unroll
            for (int t = 0; t < 4; ++t) {
                #pragma unroll
                for (int p = 0; p < 4; ++p) {
                    int seg = tid + p * 256;
                    int row = seg >> 3;
                    int c16 = seg & 7;
                    uint4 v = *(const uint4*)&srcs[t][(rbs[t] + row) * En + kc * 64 + c16 * 8];
                    *(uint4*)&dsts[t][row * TP + c16 * 8] = v;
                }
            }
        }
        __syncthreads();

        #pragma unroll
        for (int ks = 0; ks < 4; ++ks) {
            const uint32_t kb = (uint32_t)(ks * 32);
            uint32_t ah[2][4], al[2][4], bb[8][2];

            #pragma unroll
            for (int mt = 0; mt < 2; ++mt)
                ldm_x4(uAh + (uint32_t)((wm + mt * 16) * TP * 2) + kb + aoff, ah[mt]);
            #pragma unroll
            for (int t2 = 0; t2 < 4; ++t2) {
                uint32_t q[4];
                ldm_x4(uBh + (uint32_t)((wn + t2 * 16) * TP * 2) + kb + boff, q);
                bb[2 * t2][0] = q[0]; bb[2 * t2][1] = q[1];
                bb[2 * t2 + 1][0] = q[2]; bb[2 * t2 + 1][1] = q[3];
            }
            #pragma unroll
            for (int mt = 0; mt < 2; ++mt)
                #pragma unroll
                for (int nt = 0; nt < 8; ++nt)
                    mma16816(acc[mt][nt], ah[mt], bb[nt]);

            #pragma unroll
            for (int mt = 0; mt < 2; ++mt)
                ldm_x4(uAl + (uint32_t)((wm + mt * 16) * TP * 2) + kb + aoff, al[mt]);
            #pragma unroll
            for (int mt = 0; mt < 2; ++mt)
                #pragma unroll
                for (int nt = 0; nt < 8; ++nt)
                    mma16816(acc[mt][nt], al[mt], bb[nt]);

            #pragma unroll
            for (int t2 = 0; t2 < 4; ++t2) {
                uint32_t q[4];
                ldm_x4(uBl + (uint32_t)((wn + t2 * 16) * TP * 2) + kb + boff, q);
                bb[2 * t2][0] = q[0]; bb[2 * t2][1] = q[1];
                bb[2 * t2 + 1][0] = q[2]; bb[2 * t2 + 1][1] = q[3];
            }
            #pragma unroll
            for (int mt = 0; mt < 2; ++mt)
                #pragma unroll
                for (int nt = 0; nt < 8; ++nt)
                    mma16816(acc[mt][nt], ah[mt], bb[nt]);
        }
        __syncthreads();
    }

    // ---- epilogue ----
    const float sc = (which == 0) ? SCALE : 1.0f;
    #pragma unroll
    for (int mt = 0; mt < 2; ++mt) {
        #pragma unroll
        for (int nt = 0; nt < 8; ++nt) {
            int m = m0 + wm + mt * 16 + (lane >> 2);
            int n = n0 + wn + nt * 8 + (lane & 3) * 2;
            float bx = bias[n], by = bias[n + 1];
            #pragma unroll
            for (int half = 0; half < 2; ++half) {
                int mm = m + half * 8;
                float v0 = (acc[mt][nt][half * 2 + 0] + bx) * sc;
                float v1 = (acc[mt][nt][half * 2 + 1] + by) * sc;
                if (which == 3) {
                    *(float2*)&out[mm * En + n] = make_float2(v0, v1);
                } else {
                    int h = n >> 6, d = n & 63;
                    int b = mm >> 11, s = mm & 2047;
                    __nv_bfloat162 hv = __floats2bfloat162_rn(v0, v1);
                    __nv_bfloat162 lv = __floats2bfloat162_rn(
                        v0 - __bfloat162float(hv.x), v1 - __bfloat162float(hv.y));
                    if (which == 0) {
                        int idx = ((b * Hn + h) * Sn + s) * Dn + d;
                        *(__nv_bfloat162*)&g_qh[idx] = hv;
                        *(__nv_bfloat162*)&g_ql[idx] = lv;
                    } else if (which == 1) {
                        int idx = ((b * Hn + h) * Sn + s) * Dn + d;
                        *(__nv_bfloat162*)&g_kh[idx] = hv;
                        *(__nv_bfloat162*)&g_kl[idx] = lv;
                    } else {
                        int base = ((b * Hn + h) * Dn + d) * Sn + s;
                        g_vth[base] = hv.x;       g_vtl[base] = lv.x;
                        g_vth[base + Sn] = hv.y;  g_vtl[base + Sn] = lv.y;
                    }
                }
            }
        }
    }
}

// ---------------------------------------------------------------------------
// Attention: mma.sync split-bf16, flash-style, decay via smem table.
// CTA = (bh, 128 queries); key tiles of 64. 8 warps, warp = 16-row stripe.
// ---------------------------------------------------------------------------
constexpr int TPQ = 72;
// smem element offsets (bf16)
constexpr int OQH = 0;
constexpr int OQL = 128 * TPQ;            // 9216
constexpr int OKH = 2 * 128 * TPQ;        // 18432
constexpr int OKL = OKH + 64 * TPQ;       // 23040
constexpr int OVH = OKL + 64 * TPQ;       // 27648
constexpr int OVL = OVH + 64 * TPQ;       // 32256
constexpr int SM_BF16 = OVL + 64 * TPQ;   // 36864 elements
constexpr int SMEM_ATTN = SM_BF16 * 2 + 2048 * 4;  // 73728 + 8192 = 81920 B

__global__ void __launch_bounds__(256, 2)
attn_mma()
{
    extern __shared__ char smc[];
    __nv_bfloat16* smb = (__nv_bfloat16*)smc;
    float* sDec = (float*)(smc + SM_BF16 * 2);

    const int bh = blockIdx.y;
    const int q0 = blockIdx.x * 128;
    const __nv_bfloat16* Qh = g_qh + bh * Sn * Dn;
    const __nv_bfloat16* Ql = g_ql + bh * Sn * Dn;
    const __nv_bfloat16* Kh = g_kh + bh * Sn * Dn;
    const __nv_bfloat16* Kl = g_kl + bh * Sn * Dn;
    const __nv_bfloat16* Vth = g_vth + bh * Sn * Dn;
    const __nv_bfloat16* Vtl = g_vtl + bh * Sn * Dn;

    const int tid = threadIdx.x;
    const int lane = tid & 31;
    const int wid = tid >> 5;
    const int wm = wid * 16;

    const int g = lane >> 3, r = lane & 7;
    const uint32_t aoff = (uint32_t)((((g & 1) * 8 + r) * TPQ + (g >> 1) * 8) * 2);
    const uint32_t boff = (uint32_t)((((g >> 1) * 8 + r) * TPQ + (g & 1) * 8) * 2);
    const uint32_t base = smem_u32(smb);
    const uint32_t uQh = base + OQH * 2, uQl = base + OQL * 2;
    const uint32_t uKh = base + OKH * 2, uKl = base + OKL * 2;
    const uint32_t uVh = base + OVH * 2, uVl = base + OVL * 2;

    // decay table
    for (int t = tid; t < 2048; t += 256)
        sDec[t] = exp2f(LOG2_DECAY * (float)t);

    // load Q tile (128 x 64), hi+lo
    #pragma unroll
    for (int u = 0; u < 4; ++u) {
        int idx = tid + u * 256;
        int row = idx >> 3;
        int c8 = (idx & 7) * 8;
        *(uint4*)&smb[OQH + row * TPQ + c8] = *(const uint4*)&Qh[(q0 + row) * Dn + c8];
        *(uint4*)&smb[OQL + row * TPQ + c8] = *(const uint4*)&Ql[(q0 + row) * Dn + c8];
    }

    const int r0 = wm + (lane >> 2);
    const int i0 = q0 + r0;
    const int i1 = i0 + 8;

    float m0 = -1e30f, m1 = -1e30f, l0 = 0.f, l1 = 0.f;
    float o[8][4] = {};

    for (int kt = 0; kt < Sn / 64; ++kt) {
        const int k0 = kt * 64;
        __syncthreads();   // prior tile consumers done; covers Q/decay stores at kt=0

        // load K (64x64) and V^T (64x64) tiles, hi+lo
        #pragma unroll
        for (int u = 0; u < 2; ++u) {
            int idx = tid + u * 256;
            int row = idx >> 3;
            int c8 = (idx & 7) * 8;
            *(uint4*)&smb[OKH + row * TPQ + c8] = *(const uint4*)&Kh[(k0 + row) * Dn + c8];
            *(uint4*)&smb[OKL + row * TPQ + c8] = *(const uint4*)&Kl[(k0 + row) * Dn + c8];
            *(uint4*)&smb[OVH + row * TPQ + c8] = *(const uint4*)&Vth[row * Sn + k0 + c8];
            *(uint4*)&smb[OVL + row * TPQ + c8] = *(const uint4*)&Vtl[row * Sn + k0 + c8];
        }
        __syncthreads();

        // ---- S = Q K^T (3-pass split) ----
        float s[8][4] = {};
        #pragma unroll
        for (int ks = 0; ks < 4; ++ks) {
            const uint32_t kb = (uint32_t)(ks * 32);
            uint32_t ah[4], al[4], bb[8][2];
            ldm_x4(uQh + (uint32_t)(wm * TPQ * 2) + kb + aoff, ah);
            #pragma unroll
            for (int t2 = 0; t2 < 4; ++t2) {
                uint32_t q[4];
                ldm_x4(uKh + (uint32_t)(t2 * 16 * TPQ * 2) + kb + boff, q);
                bb[2 * t2][0] = q[0]; bb[2 * t2][1] = q[1];
                bb[2 * t2 + 1][0] = q[2]; bb[2 * t2 + 1][1] = q[3];
            }
            #pragma unroll
            for (int nt = 0; nt < 8; ++nt) mma16816(s[nt], ah, bb[nt]);

            ldm_x4(uQl + (uint32_t)(wm * TPQ * 2) + kb + aoff, al);
            #pragma unroll
            for (int nt = 0; nt < 8; ++nt) mma16816(s[nt], al, bb[nt]);

            #pragma unroll
            for (int t2 = 0; t2 < 4; ++t2) {
                uint32_t q[4];
                ldm_x4(uKl + (uint32_t)(t2 * 16 * TPQ * 2) + kb + boff, q);
                bb[2 * t2][0] = q[0]; bb[2 * t2][1] = q[1];
                bb[2 * t2 + 1][0] = q[2]; bb[2 * t2 + 1][1] = q[3];
            }
            #pragma unroll
            for (int nt = 0; nt < 8; ++nt) mma16816(s[nt], ah, bb[nt]);
        }

        // ---- decay mask (table lookup) ----
        #pragma unroll
        for (int nt = 0; nt < 8; ++nt) {
            int j = k0 + nt * 8 + (lane & 3) * 2;
            s[nt][0] *= sDec[abs(i0 - j)];
            s[nt][1] *= sDec[abs(i0 - j - 1)];
            s[nt][2] *= sDec[abs(i1 - j)];
            s[nt][3] *= sDec[abs(i1 - j - 1)];
        }

        // ---- online softmax (rows i0, i1; quad reduction) ----
        float mx0 = -1e30f, mx1 = -1e30f;
        #pragma unroll
        for (int nt = 0; nt < 8; ++nt) {
            mx0 = fmaxf(mx0, fmaxf(s[nt][0], s[nt][1]));
            mx1 = fmaxf(mx1, fmaxf(s[nt][2], s[nt][3]));
        }
        mx0 = fmaxf(mx0, __shfl_xor_sync(0xffffffffu, mx0, 1));
        mx0 = fmaxf(mx0, __shfl_xor_sync(0xffffffffu, mx0, 2));
        mx1 = fmaxf(mx1, __shfl_xor_sync(0xffffffffu, mx1, 1));
        mx1 = fmaxf(mx1, __shfl_xor_sync(0xffffffffu, mx1, 2));

        float mn0 = fmaxf(m0, mx0), mn1 = fmaxf(m1, mx1);
        float c0 = exp2f((m0 - mn0) * LOG2E);
        float c1 = exp2f((m1 - mn1) * LOG2E);
        m0 = mn0; m1 = mn1;
        l0 *= c0; l1 *= c1;
        #pragma unroll
        for (int nt = 0; nt < 8; ++nt) {
            o[nt][0] *= c0; o[nt][1] *= c0;
            o[nt][2] *= c1; o[nt][3] *= c1;
        }
        float sm0 = 0.f, sm1 = 0.f;
        #pragma unroll
        for (int nt = 0; nt < 8; ++nt) {
            s[nt][0] = exp2f((s[nt][0] - mn0) * LOG2E);
            s[nt][1] = exp2f((s[nt][1] - mn0) * LOG2E);
            s[nt][2] = exp2f((s[nt][2] - mn1) * LOG2E);
            s[nt][3] = exp2f((s[nt][3] - mn1) * LOG2E);
            sm0 += s[nt][0] + s[nt][1];
            sm1 += s[nt][2] + s[nt][3];
        }
        sm0 += __shfl_xor_sync(0xffffffffu, sm0, 1);
        sm0 += __shfl_xor_sync(0xffffffffu, sm0, 2);
        sm1 += __shfl_xor_sync(0xffffffffu, sm1, 1);
        sm1 += __shfl_xor_sync(0xffffffffu, sm1, 2);
        l0 += sm0; l1 += sm1;

        // ---- O += P V (3-pass split; P fragments from S accums) ----
        #pragma unroll
        for (int ksp = 0; ksp < 4; ++ksp) {
            uint32_t ph[4], pl[4], bb[8][2];
            const float* pa = s[2 * ksp];
            const float* pb = s[2 * ksp + 1];
            ph[0] = packbf(pa[0], pa[1]);
            ph[1] = packbf(pa[2], pa[3]);
            ph[2] = packbf(pb[0], pb[1]);
            ph[3] = packbf(pb[2], pb[3]);
            {
                __nv_bfloat162 h0 = *(__nv_bfloat162*)&ph[0];
                __nv_bfloat162 h1 = *(__nv_bfloat162*)&ph[1];
                __nv_bfloat162 h2 = *(__nv_bfloat162*)&ph[2];
                __nv_bfloat162 h3 = *(__nv_bfloat162*)&ph[3];
                pl[0] = packbf(pa[0] - __bfloat162float(h0.x), pa[1] - __bfloat162float(h0.y));
                pl[1] = packbf(pa[2] - __bfloat162float(h1.x), pa[3] - __bfloat162float(h1.y));
                pl[2] = packbf(pb[0] - __bfloat162float(h2.x), pb[1] - __bfloat162float(h2.y));
                pl[3] = packbf(pb[2] - __bfloat162float(h3.x), pb[3] - __bfloat162float(h3.y));
            }
            const uint32_t kb = (uint32_t)(ksp * 32);
            #pragma unroll
            for (int t2 = 0; t2 < 4; ++t2) {
                uint32_t q[4];
                ldm_x4(uVh + (uint32_t)(t2 * 16 * TPQ * 2) + kb + boff, q);
                bb[2 * t2][0] = q[0]; bb[2 * t2][1] = q[1];
                bb[2 * t2 + 1][0] = q[2]; bb[2 * t2 + 1][1] = q[3];
            }
            #pragma unroll
            for (int nt = 0; nt < 8; ++nt) mma16816(o[nt], ph, bb[nt]);
            #pragma unroll
            for (int nt = 0; nt < 8; ++nt) mma16816(o[nt], pl, bb[nt]);

            #pragma unroll
            for (int t2 = 0; t2 < 4; ++t2) {
                uint32_t q[4];
                ldm_x4(uVl + (uint32_t)(t2 * 16 * TPQ * 2) + kb + boff, q);
                bb[2 * t2][0] = q[0]; bb[2 * t2][1] = q[1];
                bb[2 * t2 + 1][0] = q[2]; bb[2 * t2 + 1][1] = q[3];
            }
            #pragma unroll
            for (int nt = 0; nt < 8; ++nt) mma16816(o[nt], ph, bb[nt]);
        }
    }

    // ---- epilogue: normalize, split, store to flat [m][k] ----
    const float inv0 = 1.0f / l0, inv1 = 1.0f / l1;
    const int b = bh >> 3, h = bh & 7;
    const int mf0 = b * Sn + i0;          // flat token row for i0
    const int mf1 = mf0 + 8;
    #pragma unroll
    for (int nt = 0; nt < 8; ++nt) {
        int d = nt * 8 + (lane & 3) * 2;
        int col = h * 64 + d;
        {
            float v0 = o[nt][0] * inv0, v1 = o[nt][1] * inv0;
            __nv_bfloat162 hv = __floats2bfloat162_rn(v0, v1);
            __nv_bfloat162 lv = __floats2bfloat162_rn(
                v0 - __bfloat162float(hv.x), v1 - __bfloat162float(hv.y));
            *(__nv_bfloat162*)&g_ah[mf0 * En + col] = hv;
            *(__nv_bfloat162*)&g_al[mf0 * En + col] = lv;
        }
        {
            float v0 = o[nt][2] * inv1, v1 = o[nt][3] * inv1;
            __nv_bfloat162 hv = __floats2bfloat162_rn(v0, v1);
            __nv_bfloat162 lv = __floats2bfloat162_rn(
                v0 - __bfloat162float(hv.x), v1 - __bfloat162float(hv.y));
            *(__nv_bfloat162*)&g_ah[mf1 * En + col] = hv;
            *(__nv_bfloat162*)&g_al[mf1 * En + col] = lv;
        }
    }
}

// ---------------------------------------------------------------------------
extern "C" void kernel_launch(void* const* d_in, const int* in_sizes, int n_in,
                              void* d_out, int out_size)
{
    const float* x  = (const float*)d_in[0];
    const float* Wq = (const float*)d_in[1];
    const float* bq = (const float*)d_in[2];
    const float* Wk = (const float*)d_in[3];
    const float* bk = (const float*)d_in[4];
    const float* Wv = (const float*)d_in[5];
    const float* bv = (const float*)d_in[6];
    const float* Wo = (const float*)d_in[7];
    const float* bo = (const float*)d_in[8];
    float* out = (float*)d_out;

    cudaFuncSetAttribute(gemm_mma,
                         cudaFuncAttributeMaxDynamicSharedMemorySize, GE_SMEM);
    cudaFuncSetAttribute(attn_mma,
                         cudaFuncAttributeMaxDynamicSharedMemorySize, SMEM_ATTN);

    // Split-precision conversions
    convert_split<<<2048, 256>>>(x,  0, Mtot * En);
    convert_split<<<512,  256>>>(Wq, 1, En * En);
    convert_split<<<512,  256>>>(Wk, 2, En * En);
    convert_split<<<512,  256>>>(Wv, 3, En * En);
    convert_split<<<512,  256>>>(Wo, 4, En * En);

    // QKV projections (tensor cores) -> split bf16 Q/K/V^T
    dim3 gQKV(En / 128, Mtot / 128, 3);
    gemm_mma<<<gQKV, 256, GE_SMEM>>>(bq, bk, bv, bo, out, -1);

    // Attention (tensor cores) -> split bf16 flat [m][k]
    dim3 gAttn(Sn / 128, BH);
    attn_mma<<<gAttn, 256, SMEM_ATTN>>>();

    // Output projection
    dim3 gOut(En / 128, Mtot / 128, 1);
    gemm_mma<<<gOut, 256, GE_SMEM>>>(bq, bk, bv, bo, out, 3);
}

// round 8
// speedup vs baseline: 5.1420x; 1.6630x over previous
#include <cuda_runtime.h>
#include <cuda_bf16.h>
#include <cstdint>

// Problem constants
constexpr int Bn = 4;
constexpr int Sn = 2048;
constexpr int En = 512;
constexpr int Hn = 8;
constexpr int Dn = 64;
constexpr int Mtot = Bn * Sn;   // 8192
constexpr int BH = Bn * Hn;     // 32

constexpr float SCALE = 0.125f;                 // 1/sqrt(64)
constexpr float LOG2_DECAY = -0.07400058144377693f; // log2(0.95)
constexpr float LOG2E = 1.4426950408889634f;

// ---------------------------------------------------------------------------
// Scratch (device globals — no allocation allowed)
// ---------------------------------------------------------------------------
__device__ __nv_bfloat16 g_xh[Mtot * En];
__device__ __nv_bfloat16 g_xl[Mtot * En];
__device__ __nv_bfloat16 g_wh[4 * En * En];   // slots: Wq, Wk, Wv, Wo
__device__ __nv_bfloat16 g_wl[4 * En * En];

// split-bf16 Q (pre-scaled), K: [B,H,S,D]; V transposed: [B,H,D,S]
__device__ __nv_bfloat16 g_qh[BH * Sn * Dn];
__device__ __nv_bfloat16 g_ql[BH * Sn * Dn];
__device__ __nv_bfloat16 g_kh[BH * Sn * Dn];
__device__ __nv_bfloat16 g_kl[BH * Sn * Dn];
__device__ __nv_bfloat16 g_vth[BH * Sn * Dn];
__device__ __nv_bfloat16 g_vtl[BH * Sn * Dn];

// attention output, flat [m][k] (k = h*64+d), split
__device__ __nv_bfloat16 g_ah[Mtot * En];
__device__ __nv_bfloat16 g_al[Mtot * En];

// cumulative per-tile V sums: g_vsum[bh][t][d] = sum of v[j][d] over tiles < t
__device__ float g_vsum[BH * 33 * 64];

// ---------------------------------------------------------------------------
// mma.sync helpers
// ---------------------------------------------------------------------------
__device__ __forceinline__ uint32_t smem_u32(const void* p) {
    uint32_t a;
    asm("{ .reg .u64 t; cvta.to.shared.u64 t, %1; cvt.u32.u64 %0, t; }"
        : "=r"(a) : "l"(p));
    return a;
}

__device__ __forceinline__ void ldm_x4(uint32_t addr, uint32_t* r) {
    asm volatile("ldmatrix.sync.aligned.m8n8.x4.shared.b16 {%0,%1,%2,%3}, [%4];"
                 : "=r"(r[0]), "=r"(r[1]), "=r"(r[2]), "=r"(r[3]) : "r"(addr));
}

__device__ __forceinline__ void mma16816(float* c, const uint32_t* a, const uint32_t* b) {
    asm volatile(
        "mma.sync.aligned.m16n8k16.row.col.f32.bf16.bf16.f32 "
        "{%0,%1,%2,%3}, {%4,%5,%6,%7}, {%8,%9}, {%0,%1,%2,%3};"
        : "+f"(c[0]), "+f"(c[1]), "+f"(c[2]), "+f"(c[3])
        : "r"(a[0]), "r"(a[1]), "r"(a[2]), "r"(a[3]), "r"(b[0]), "r"(b[1]));
}

__device__ __forceinline__ uint32_t packbf(float e0, float e1) {
    __nv_bfloat162 h = __floats2bfloat162_rn(e0, e1);   // .x = e0 (low)
    return *(uint32_t*)&h;
}

// ---------------------------------------------------------------------------
// Conversion kernels: fp32 -> (hi, lo) bf16 pair
// ---------------------------------------------------------------------------
__global__ void convert_x(const float* __restrict__ src, int n)
{
    for (int i = blockIdx.x * blockDim.x + threadIdx.x; i < n;
         i += gridDim.x * blockDim.x) {
        float v = src[i];
        __nv_bfloat16 h = __float2bfloat16(v);
        g_xh[i] = h;
        g_xl[i] = __float2bfloat16(v - __bfloat162float(h));
    }
}

__global__ void convert_w(const float* __restrict__ Wq, const float* __restrict__ Wk,
                          const float* __restrict__ Wv, const float* __restrict__ Wo)
{
    const int n = 4 * En * En;
    for (int i = blockIdx.x * blockDim.x + threadIdx.x; i < n;
         i += gridDim.x * blockDim.x) {
        int w = i >> 18;                      // En*En = 262144 = 2^18
        int off = i & (En * En - 1);
        const float* src = (w == 0) ? Wq : (w == 1) ? Wk : (w == 2) ? Wv : Wo;
        float v = src[off];
        __nv_bfloat16 h = __float2bfloat16(v);
        g_wh[i] = h;
        g_wl[i] = __float2bfloat16(v - __bfloat162float(h));
    }
}

// ---------------------------------------------------------------------------
// Per-tile V sums -> cumulative boundary table (one block per bh, 512 thr)
// ---------------------------------------------------------------------------
__global__ void vtile_sums()
{
    const int bh = blockIdx.x;
    const int t = threadIdx.x;          // 0..511
    const int d = t >> 3;
    const int sl = t & 7;
    const __nv_bfloat16* vh = g_vth + bh * Sn * Dn + d * Sn;
    const __nv_bfloat16* vl = g_vtl + bh * Sn * Dn + d * Sn;

    __shared__ float tile_s[32][64];

    for (int tt = 0; tt < 32; ++tt) {
        float acc = 0.f;
        #pragma unroll
        for (int u = 0; u < 8; ++u) {
            int s = tt * 64 + sl + u * 8;
            acc += __bfloat162float(vh[s]) + __bfloat162float(vl[s]);
        }
        acc += __shfl_xor_sync(0xffffffffu, acc, 1);
        acc += __shfl_xor_sync(0xffffffffu, acc, 2);
        acc += __shfl_xor_sync(0xffffffffu, acc, 4);
        if (sl == 0) tile_s[tt][d] = acc;
    }
    __syncthreads();
    if (t < 64) {
        float run = 0.f;
        #pragma unroll
        for (int tt = 0; tt <= 32; ++tt) {
            g_vsum[(bh * 33 + tt) * 64 + t] = run;
            if (tt < 32) run += tile_s[tt][t];
        }
    }
}

// ---------------------------------------------------------------------------
// mma.sync split-bf16 GEMM (unchanged from R7-passing version)
// ---------------------------------------------------------------------------
constexpr int TP = 72;
constexpr int TILE_ELE = 128 * TP;
constexpr int GE_SMEM = 4 * TILE_ELE * 2;  // 73728 B

__global__ void __launch_bounds__(256, 2)
gemm_mma(const float* __restrict__ bq, const float* __restrict__ bk,
         const float* __restrict__ bv, const float* __restrict__ bo,
         float* __restrict__ out, int which_arg)
{
    extern __shared__ __nv_bfloat16 smb[];
    __nv_bfloat16* sAh = smb;
    __nv_bfloat16* sAl = sAh + TILE_ELE;
    __nv_bfloat16* sBh = sAl + TILE_ELE;
    __nv_bfloat16* sBl = sBh + TILE_ELE;

    const int tid  = threadIdx.x;
    const int lane = tid & 31;
    const int wid  = tid >> 5;
    const int which = (which_arg < 0) ? (int)blockIdx.z : which_arg;

    const __nv_bfloat16* Ah = (which < 3) ? g_xh : g_ah;
    const __nv_bfloat16* Al = (which < 3) ? g_xl : g_al;
    const __nv_bfloat16* Bh = g_wh + which * En * En;
    const __nv_bfloat16* Bl = g_wl + which * En * En;
    const float* bias = (which == 0) ? bq : (which == 1) ? bk :
                        (which == 2) ? bv : bo;

    const int n0 = blockIdx.x * 128;
    const int m0 = blockIdx.y * 128;
    const int wm = (wid & 3) * 32;
    const int wn = (wid >> 2) * 64;

    const int g = lane >> 3, r = lane & 7;
    const uint32_t aoff = (uint32_t)((((g & 1) * 8 + r) * TP + (g >> 1) * 8) * 2);
    const uint32_t boff = (uint32_t)((((g >> 1) * 8 + r) * TP + (g & 1) * 8) * 2);
    const uint32_t uAh = smem_u32(sAh), uAl = smem_u32(sAl);
    const uint32_t uBh = smem_u32(sBh), uBl = smem_u32(sBl);

    float acc[2][8][4] = {};

    for (int kc = 0; kc < 8; ++kc) {
        {
            const __nv_bfloat16* srcs[4] = {Ah, Al, Bh, Bl};
            __nv_bfloat16* dsts[4] = {sAh, sAl, sBh, sBl};
            const int rbs[4] = {m0, m0, n0, n0};
            #pragma unroll
            for (int t = 0; t < 4; ++t) {
                #pragma unroll
                for (int p = 0; p < 4; ++p) {
                    int seg = tid + p * 256;
                    int row = seg >> 3;
                    int c16 = seg & 7;
                    uint4 v = *(const uint4*)&srcs[t][(rbs[t] + row) * En + kc * 64 + c16 * 8];
                    *(uint4*)&dsts[t][row * TP + c16 * 8] = v;
                }
            }
        }
        __syncthreads();

        #pragma unroll
        for (int ks = 0; ks < 4; ++ks) {
            const uint32_t kb = (uint32_t)(ks * 32);
            uint32_t ah[2][4], al[2][4], bb[8][2];

            #pragma unroll
            for (int mt = 0; mt < 2; ++mt)
                ldm_x4(uAh + (uint32_t)((wm + mt * 16) * TP * 2) + kb + aoff, ah[mt]);
            #pragma unroll
            for (int t2 = 0; t2 < 4; ++t2) {
                uint32_t q[4];
                ldm_x4(uBh + (uint32_t)((wn + t2 * 16) * TP * 2) + kb + boff, q);
                bb[2 * t2][0] = q[0]; bb[2 * t2][1] = q[1];
                bb[2 * t2 + 1][0] = q[2]; bb[2 * t2 + 1][1] = q[3];
            }
            #pragma unroll
            for (int mt = 0; mt < 2; ++mt)
                #pragma unroll
                for (int nt = 0; nt < 8; ++nt)
                    mma16816(acc[mt][nt], ah[mt], bb[nt]);

            #pragma unroll
            for (int mt = 0; mt < 2; ++mt)
                ldm_x4(uAl + (uint32_t)((wm + mt * 16) * TP * 2) + kb + aoff, al[mt]);
            #pragma unroll
            for (int mt = 0; mt < 2; ++mt)
                #pragma unroll
                for (int nt = 0; nt < 8; ++nt)
                    mma16816(acc[mt][nt], al[mt], bb[nt]);

            #pragma unroll
            for (int t2 = 0; t2 < 4; ++t2) {
                uint32_t q[4];
                ldm_x4(uBl + (uint32_t)((wn + t2 * 16) * TP * 2) + kb + boff, q);
                bb[2 * t2][0] = q[0]; bb[2 * t2][1] = q[1];
                bb[2 * t2 + 1][0] = q[2]; bb[2 * t2 + 1][1] = q[3];
            }
            #pragma unroll
            for (int mt = 0; mt < 2; ++mt)
                #pragma unroll
                for (int nt = 0; nt < 8; ++nt)
                    mma16816(acc[mt][nt], ah[mt], bb[nt]);
        }
        __syncthreads();
    }

    const float sc = (which == 0) ? SCALE : 1.0f;
    #pragma unroll
    for (int mt = 0; mt < 2; ++mt) {
        #pragma unroll
        for (int nt = 0; nt < 8; ++nt) {
            int m = m0 + wm + mt * 16 + (lane >> 2);
            int n = n0 + wn + nt * 8 + (lane & 3) * 2;
            float bx = bias[n], by = bias[n + 1];
            #pragma unroll
            for (int half = 0; half < 2; ++half) {
                int mm = m + half * 8;
                float v0 = (acc[mt][nt][half * 2 + 0] + bx) * sc;
                float v1 = (acc[mt][nt][half * 2 + 1] + by) * sc;
                if (which == 3) {
                    *(float2*)&out[mm * En + n] = make_float2(v0, v1);
                } else {
                    int h = n >> 6, d = n & 63;
                    int b = mm >> 11, s = mm & 2047;
                    __nv_bfloat162 hv = __floats2bfloat162_rn(v0, v1);
                    __nv_bfloat162 lv = __floats2bfloat162_rn(
                        v0 - __bfloat162float(hv.x), v1 - __bfloat162float(hv.y));
                    if (which == 0) {
                        int idx = ((b * Hn + h) * Sn + s) * Dn + d;
                        *(__nv_bfloat162*)&g_qh[idx] = hv;
                        *(__nv_bfloat162*)&g_ql[idx] = lv;
                    } else if (which == 1) {
                        int idx = ((b * Hn + h) * Sn + s) * Dn + d;
                        *(__nv_bfloat162*)&g_kh[idx] = hv;
                        *(__nv_bfloat162*)&g_kl[idx] = lv;
                    } else {
                        int base = ((b * Hn + h) * Dn + d) * Sn + s;
                        g_vth[base] = hv.x;       g_vtl[base] = lv.x;
                        g_vth[base + Sn] = hv.y;  g_vtl[base + Sn] = lv.y;
                    }
                }
            }
        }
    }
}

// ---------------------------------------------------------------------------
// Attention: mma.sync split-bf16 flash, decay-windowed (|i-j| <= 256 exact,
// far field analytic via V prefix sums). CTA = (bh, 128 queries).
// ---------------------------------------------------------------------------
constexpr int TPQ = 72;
constexpr int OQH = 0;
constexpr int OQL = 128 * TPQ;
constexpr int OKH = 2 * 128 * TPQ;
constexpr int OKL = OKH + 64 * TPQ;
constexpr int OVH = OKL + 64 * TPQ;
constexpr int OVL = OVH + 64 * TPQ;
constexpr int SM_BF16 = OVL + 64 * TPQ;             // 36864 elements
constexpr int SMEM_ATTN = SM_BF16 * 2 + 512 * 4;    // 73728 + 2048 = 75776 B

__global__ void __launch_bounds__(256, 2)
attn_mma()
{
    extern __shared__ char smc[];
    __nv_bfloat16* smb = (__nv_bfloat16*)smc;
    float* sDec = (float*)(smc + SM_BF16 * 2);

    const int bh = blockIdx.y;
    const int q0 = blockIdx.x * 128;
    const __nv_bfloat16* Qh = g_qh + bh * Sn * Dn;
    const __nv_bfloat16* Ql = g_ql + bh * Sn * Dn;
    const __nv_bfloat16* Kh = g_kh + bh * Sn * Dn;
    const __nv_bfloat16* Kl = g_kl + bh * Sn * Dn;
    const __nv_bfloat16* Vth = g_vth + bh * Sn * Dn;
    const __nv_bfloat16* Vtl = g_vtl + bh * Sn * Dn;

    const int tid = threadIdx.x;
    const int lane = tid & 31;
    const int wid = tid >> 5;
    const int wm = wid * 16;

    const int g = lane >> 3, r = lane & 7;
    const uint32_t aoff = (uint32_t)((((g & 1) * 8 + r) * TPQ + (g >> 1) * 8) * 2);
    const uint32_t boff = (uint32_t)((((g >> 1) * 8 + r) * TPQ + (g & 1) * 8) * 2);
    const uint32_t base = smem_u32(smb);
    const uint32_t uQh = base + OQH * 2, uQl = base + OQL * 2;
    const uint32_t uKh = base + OKH * 2, uKl = base + OKL * 2;
    const uint32_t uVh = base + OVH * 2, uVl = base + OVL * 2;

    // decay table (|i-j| <= 446 within processed window)
    for (int t = tid; t < 512; t += 256)
        sDec[t] = exp2f(LOG2_DECAY * (float)t);

    // load Q tile (128 x 64), hi+lo
    #pragma unroll
    for (int u = 0; u < 4; ++u) {
        int idx = tid + u * 256;
        int row = idx >> 3;
        int c8 = (idx & 7) * 8;
        *(uint4*)&smb[OQH + row * TPQ + c8] = *(const uint4*)&Qh[(q0 + row) * Dn + c8];
        *(uint4*)&smb[OQL + row * TPQ + c8] = *(const uint4*)&Ql[(q0 + row) * Dn + c8];
    }

    const int r0 = wm + (lane >> 2);
    const int i0 = q0 + r0;
    const int i1 = i0 + 8;

    // windowed tile range: keys with |i-j| <= 256 fully covered
    const int t_lo = max(0, (q0 >> 6) - 4);
    const int t_hi = min(32, (q0 >> 6) + 6);
    const float nfar = (float)((t_lo << 6) + (Sn - (t_hi << 6)));

    // far-field init: m = 0 (decayed far scores ~ 0), l = N_far, o = sum_far v
    float m0 = 0.f, m1 = 0.f, l0 = nfar, l1 = nfar;
    float o[8][4];
    {
        const float* vs_lo  = &g_vsum[(bh * 33 + t_lo) * 64];
        const float* vs_hi  = &g_vsum[(bh * 33 + t_hi) * 64];
        const float* vs_all = &g_vsum[(bh * 33 + 32) * 64];
        #pragma unroll
        for (int nt = 0; nt < 8; ++nt) {
            int d = nt * 8 + (lane & 3) * 2;
            float vf0 = vs_lo[d]     + vs_all[d]     - vs_hi[d];
            float vf1 = vs_lo[d + 1] + vs_all[d + 1] - vs_hi[d + 1];
            o[nt][0] = vf0; o[nt][1] = vf1;
            o[nt][2] = vf0; o[nt][3] = vf1;
        }
    }

    for (int kt = t_lo; kt < t_hi; ++kt) {
        const int k0 = kt * 64;
        __syncthreads();   // prior tile consumers done; covers Q/decay stores on 1st iter

        #pragma unroll
        for (int u = 0; u < 2; ++u) {
            int idx = tid + u * 256;
            int row = idx >> 3;
            int c8 = (idx & 7) * 8;
            *(uint4*)&smb[OKH + row * TPQ + c8] = *(const uint4*)&Kh[(k0 + row) * Dn + c8];
            *(uint4*)&smb[OKL + row * TPQ + c8] = *(const uint4*)&Kl[(k0 + row) * Dn + c8];
            *(uint4*)&smb[OVH + row * TPQ + c8] = *(const uint4*)&Vth[row * Sn + k0 + c8];
            *(uint4*)&smb[OVL + row * TPQ + c8] = *(const uint4*)&Vtl[row * Sn + k0 + c8];
        }
        __syncthreads();

        // ---- S = Q K^T (3-pass split) ----
        float s[8][4] = {};
        #pragma unroll
        for (int ks = 0; ks < 4; ++ks) {
            const uint32_t kb = (uint32_t)(ks * 32);
            uint32_t ah[4], al[4], bb[8][2];
            ldm_x4(uQh + (uint32_t)(wm * TPQ * 2) + kb + aoff, ah);
            #pragma unroll
            for (int t2 = 0; t2 < 4; ++t2) {
                uint32_t q[4];
                ldm_x4(uKh + (uint32_t)(t2 * 16 * TPQ * 2) + kb + boff, q);
                bb[2 * t2][0] = q[0]; bb[2 * t2][1] = q[1];
                bb[2 * t2 + 1][0] = q[2]; bb[2 * t2 + 1][1] = q[3];
            }
            #pragma unroll
            for (int nt = 0; nt < 8; ++nt) mma16816(s[nt], ah, bb[nt]);

            ldm_x4(uQl + (uint32_t)(wm * TPQ * 2) + kb + aoff, al);
            #pragma unroll
            for (int nt = 0; nt < 8; ++nt) mma16816(s[nt], al, bb[nt]);

            #pragma unroll
            for (int t2 = 0; t2 < 4; ++t2) {
                uint32_t q[4];
                ldm_x4(uKl + (uint32_t)(t2 * 16 * TPQ * 2) + kb + boff, q);
                bb[2 * t2][0] = q[0]; bb[2 * t2][1] = q[1];
                bb[2 * t2 + 1][0] = q[2]; bb[2 * t2 + 1][1] = q[3];
            }
            #pragma unroll
            for (int nt = 0; nt < 8; ++nt) mma16816(s[nt], ah, bb[nt]);
        }

        // ---- decay mask ----
        #pragma unroll
        for (int nt = 0; nt < 8; ++nt) {
            int j = k0 + nt * 8 + (lane & 3) * 2;
            s[nt][0] *= sDec[abs(i0 - j)];
            s[nt][1] *= sDec[abs(i0 - j - 1)];
            s[nt][2] *= sDec[abs(i1 - j)];
            s[nt][3] *= sDec[abs(i1 - j - 1)];
        }

        // ---- online softmax ----
        float mx0 = -1e30f, mx1 = -1e30f;
        #pragma unroll
        for (int nt = 0; nt < 8; ++nt) {
            mx0 = fmaxf(mx0, fmaxf(s[nt][0], s[nt][1]));
            mx1 = fmaxf(mx1, fmaxf(s[nt][2], s[nt][3]));
        }
        mx0 = fmaxf(mx0, __shfl_xor_sync(0xffffffffu, mx0, 1));
        mx0 = fmaxf(mx0, __shfl_xor_sync(0xffffffffu, mx0, 2));
        mx1 = fmaxf(mx1, __shfl_xor_sync(0xffffffffu, mx1, 1));
        mx1 = fmaxf(mx1, __shfl_xor_sync(0xffffffffu, mx1, 2));

        float mn0 = fmaxf(m0, mx0), mn1 = fmaxf(m1, mx1);
        float c0 = exp2f((m0 - mn0) * LOG2E);
        float c1 = exp2f((m1 - mn1) * LOG2E);
        m0 = mn0; m1 = mn1;
        l0 *= c0; l1 *= c1;
        #pragma unroll
        for (int nt = 0; nt < 8; ++nt) {
            o[nt][0] *= c0; o[nt][1] *= c0;
            o[nt][2] *= c1; o[nt][3] *= c1;
        }
        float sm0 = 0.f, sm1 = 0.f;
        #pragma unroll
        for (int nt = 0; nt < 8; ++nt) {
            s[nt][0] = exp2f((s[nt][0] - mn0) * LOG2E);
            s[nt][1] = exp2f((s[nt][1] - mn0) * LOG2E);
            s[nt][2] = exp2f((s[nt][2] - mn1) * LOG2E);
            s[nt][3] = exp2f((s[nt][3] - mn1) * LOG2E);
            sm0 += s[nt][0] + s[nt][1];
            sm1 += s[nt][2] + s[nt][3];
        }
        sm0 += __shfl_xor_sync(0xffffffffu, sm0, 1);
        sm0 += __shfl_xor_sync(0xffffffffu, sm0, 2);
        sm1 += __shfl_xor_sync(0xffffffffu, sm1, 1);
        sm1 += __shfl_xor_sync(0xffffffffu, sm1, 2);
        l0 += sm0; l1 += sm1;

        // ---- O += P V (3-pass split) ----
        #pragma unroll
        for (int ksp = 0; ksp < 4; ++ksp) {
            uint32_t ph[4], pl[4], bb[8][2];
            const float* pa = s[2 * ksp];
            const float* pb = s[2 * ksp + 1];
            ph[0] = packbf(pa[0], pa[1]);
            ph[1] = packbf(pa[2], pa[3]);
            ph[2] = packbf(pb[0], pb[1]);
            ph[3] = packbf(pb[2], pb[3]);
            {
                __nv_bfloat162 h0 = *(__nv_bfloat162*)&ph[0];
                __nv_bfloat162 h1 = *(__nv_bfloat162*)&ph[1];
                __nv_bfloat162 h2 = *(__nv_bfloat162*)&ph[2];
                __nv_bfloat162 h3 = *(__nv_bfloat162*)&ph[3];
                pl[0] = packbf(pa[0] - __bfloat162float(h0.x), pa[1] - __bfloat162float(h0.y));
                pl[1] = packbf(pa[2] - __bfloat162float(h1.x), pa[3] - __bfloat162float(h1.y));
                pl[2] = packbf(pb[0] - __bfloat162float(h2.x), pb[1] - __bfloat162float(h2.y));
                pl[3] = packbf(pb[2] - __bfloat162float(h3.x), pb[3] - __bfloat162float(h3.y));
            }
            const uint32_t kb = (uint32_t)(ksp * 32);
            #pragma unroll
            for (int t2 = 0; t2 < 4; ++t2) {
                uint32_t q[4];
                ldm_x4(uVh + (uint32_t)(t2 * 16 * TPQ * 2) + kb + boff, q);
                bb[2 * t2][0] = q[0]; bb[2 * t2][1] = q[1];
                bb[2 * t2 + 1][0] = q[2]; bb[2 * t2 + 1][1] = q[3];
            }
            #pragma unroll
            for (int nt = 0; nt < 8; ++nt) mma16816(o[nt], ph, bb[nt]);
            #pragma unroll
            for (int nt = 0; nt < 8; ++nt) mma16816(o[nt], pl, bb[nt]);

            #pragma unroll
            for (int t2 = 0; t2 < 4; ++t2) {
                uint32_t q[4];
                ldm_x4(uVl + (uint32_t)(t2 * 16 * TPQ * 2) + kb + boff, q);
                bb[2 * t2][0] = q[0]; bb[2 * t2][1] = q[1];
                bb[2 * t2 + 1][0] = q[2]; bb[2 * t2 + 1][1] = q[3];
            }
            #pragma unroll
            for (int nt = 0; nt < 8; ++nt) mma16816(o[nt], ph, bb[nt]);
        }
    }

    // ---- epilogue: normalize, split, store to flat [m][k] ----
    const float inv0 = 1.0f / l0, inv1 = 1.0f / l1;
    const int b = bh >> 3, h = bh & 7;
    const int mf0 = b * Sn + i0;
    const int mf1 = mf0 + 8;
    #pragma unroll
    for (int nt = 0; nt < 8; ++nt) {
        int d = nt * 8 + (lane & 3) * 2;
        int col = h * 64 + d;
        {
            float v0 = o[nt][0] * inv0, v1 = o[nt][1] * inv0;
            __nv_bfloat162 hv = __floats2bfloat162_rn(v0, v1);
            __nv_bfloat162 lv = __floats2bfloat162_rn(
                v0 - __bfloat162float(hv.x), v1 - __bfloat162float(hv.y));
            *(__nv_bfloat162*)&g_ah[mf0 * En + col] = hv;
            *(__nv_bfloat162*)&g_al[mf0 * En + col] = lv;
        }
        {
            float v0 = o[nt][2] * inv1, v1 = o[nt][3] * inv1;
            __nv_bfloat162 hv = __floats2bfloat162_rn(v0, v1);
            __nv_bfloat162 lv = __floats2bfloat162_rn(
                v0 - __bfloat162float(hv.x), v1 - __bfloat162float(hv.y));
            *(__nv_bfloat162*)&g_ah[mf1 * En + col] = hv;
            *(__nv_bfloat162*)&g_al[mf1 * En + col] = lv;
        }
    }
}

// ---------------------------------------------------------------------------
extern "C" void kernel_launch(void* const* d_in, const int* in_sizes, int n_in,
                              void* d_out, int out_size)
{
    const float* x  = (const float*)d_in[0];
    const float* Wq = (const float*)d_in[1];
    const float* bq = (const float*)d_in[2];
    const float* Wk = (const float*)d_in[3];
    const float* bk = (const float*)d_in[4];
    const float* Wv = (const float*)d_in[5];
    const float* bv = (const float*)d_in[6];
    const float* Wo = (const float*)d_in[7];
    const float* bo = (const float*)d_in[8];
    float* out = (float*)d_out;

    cudaFuncSetAttribute(gemm_mma,
                         cudaFuncAttributeMaxDynamicSharedMemorySize, GE_SMEM);
    cudaFuncSetAttribute(attn_mma,
                         cudaFuncAttributeMaxDynamicSharedMemorySize, SMEM_ATTN);

    // Split-precision conversions
    convert_x<<<2048, 256>>>(x, Mtot * En);
    convert_w<<<2048, 256>>>(Wq, Wk, Wv, Wo);

    // QKV projections (tensor cores) -> split bf16 Q/K/V^T
    dim3 gQKV(En / 128, Mtot / 128, 3);
    gemm_mma<<<gQKV, 256, GE_SMEM>>>(bq, bk, bv, bo, out, -1);

    // Per-tile V prefix sums (far-field table)
    vtile_sums<<<BH, 512>>>();

    // Attention (tensor cores, decay-windowed)
    dim3 gAttn(Sn / 128, BH);
    attn_mma<<<gAttn, 256, SMEM_ATTN>>>();

    // Output projection
    dim3 gOut(En / 128, Mtot / 128, 1);
    gemm_mma<<<gOut, 256, GE_SMEM>>>(bq, bk, bv, bo, out, 3);
}